// round 7
// baseline (speedup 1.0000x reference)
#include <cuda_runtime.h>
#include <cuda_fp16.h>
#include <math.h>
#include <stdint.h>

#define BATCH 4096
#define SQ    64
#define DM    256
#define FFD   1024
#define NL    6
#define MTOK  (BATCH*SQ)

// ---------------- scratch ----------------
__device__ float g_x[MTOK*DM];
__device__ float g_qkv[MTOK*3*DM];
__device__ float g_y[MTOK*DM];
__device__ float g_pe[SQ*DM];
__device__ float g_vh[BATCH*DM];
__device__ float g_ch[BATCH*DM];

__device__ __half g_xh[MTOK*DM];    __device__ uint8_t g_x8h[MTOK*DM], g_x8l[MTOK*DM];
__device__ __half g_oh[MTOK*DM];    __device__ uint8_t g_o8h[MTOK*DM], g_o8l[MTOK*DM];
__device__ __half g_fh[MTOK*FFD];   __device__ uint8_t g_f8h[MTOK*FFD], g_f8l[MTOK*FFD];
__device__ __half g_h1h[BATCH*1024];__device__ uint8_t g_h18h[BATCH*1024], g_h18l[BATCH*1024];
__device__ __half g_ph[BATCH*DM];   __device__ uint8_t g_p8h[BATCH*DM], g_p8l[BATCH*DM];

#define OFF_QKV 0UL
#define OFF_OUT 1179648UL
#define OFF_FF1 1572864UL
#define OFF_FF2 3145728UL
#define OFF_VW1 4718592UL
#define OFF_CW1 4784128UL
#define OFF_PW1 4849664UL
#define OFF_PW2 21626880UL
#define WPOOL   25821184UL
__device__ __half g_wpH[WPOOL];     __device__ uint8_t g_wp8h[WPOOL], g_wp8l[WPOOL];

// ---------------- helpers ----------------
__device__ __forceinline__ uint16_t f8pair(float b1, float b0) {
    uint16_t r;
    asm("cvt.rn.satfinite.e4m3x2.f32 %0, %1, %2;" : "=h"(r) : "f"(b1), "f"(b0));
    return r;
}

__device__ __forceinline__ void store1(__half* H, uint8_t* E, uint8_t* L, size_t o, float v) {
    __half h = __float2half(v);
    float hf = __half2float(h);
    H[o] = h;
    E[o] = (uint8_t)f8pair(0.0f, hf);
    L[o] = (uint8_t)f8pair(0.0f, (v - hf) * 4096.0f);
}

__device__ __forceinline__ void mma_f16(float* c, const uint32_t* a, const uint32_t* b) {
    asm volatile(
        "mma.sync.aligned.m16n8k16.row.col.f32.f16.f16.f32 "
        "{%0,%1,%2,%3}, {%4,%5,%6,%7}, {%8,%9}, {%0,%1,%2,%3};\n"
        : "+f"(c[0]), "+f"(c[1]), "+f"(c[2]), "+f"(c[3])
        : "r"(a[0]), "r"(a[1]), "r"(a[2]), "r"(a[3]), "r"(b[0]), "r"(b[1]));
}

__device__ __forceinline__ void mma_f8(float* c, const uint32_t* a, const uint32_t* b) {
    asm volatile(
        "mma.sync.aligned.m16n8k32.row.col.f32.e4m3.e4m3.f32 "
        "{%0,%1,%2,%3}, {%4,%5,%6,%7}, {%8,%9}, {%0,%1,%2,%3};\n"
        : "+f"(c[0]), "+f"(c[1]), "+f"(c[2]), "+f"(c[3])
        : "r"(a[0]), "r"(a[1]), "r"(a[2]), "r"(a[3]), "r"(b[0]), "r"(b[1]));
}

__device__ __forceinline__ void ldsm4(uint32_t& r0, uint32_t& r1, uint32_t& r2, uint32_t& r3,
                                      uint32_t a) {
    asm volatile("ldmatrix.sync.aligned.m8n8.x4.shared.b16 {%0,%1,%2,%3}, [%4];"
                 : "=r"(r0), "=r"(r1), "=r"(r2), "=r"(r3) : "r"(a));
}

__device__ __forceinline__ void cpa16(uint32_t s, const void* g) {
    asm volatile("cp.async.cg.shared.global [%0], [%1], 16;" :: "r"(s), "l"(g));
}

// ---------------- split kernel (weights) ----------------
__global__ void split_kernel(const float* __restrict__ in, __half* __restrict__ H,
                             uint8_t* __restrict__ E, uint8_t* __restrict__ L, int n4) {
    int i = blockIdx.x * 256 + threadIdx.x;
    if (i >= n4) return;
    float4 v = ((const float4*)in)[i];
    size_t o = (size_t)i * 4;
    store1(H, E, L, o,     v.x);
    store1(H, E, L, o + 1, v.y);
    store1(H, E, L, o + 2, v.z);
    store1(H, E, L, o + 3, v.w);
}

// ---------------- PE ----------------
__global__ void pe_kernel(float* __restrict__ pe) {
    int s = blockIdx.x, d = threadIdx.x;
    int row = s >> 3, col = s & 7;
    float div = powf(10000.0f, (2.0f * (float)(d >> 1)) / 256.0f);
    pe[s * DM + d] = (d & 1) ? cosf((float)col / div) : sinf((float)row / div);
}

// ---------------- embed ----------------
__global__ void embed_kernel(const float* __restrict__ board, const float* __restrict__ emb,
                             const float* __restrict__ pe, float* __restrict__ x,
                             __half* __restrict__ H, uint8_t* __restrict__ E,
                             uint8_t* __restrict__ L) {
    int tokidx = blockIdx.x;
    int b = tokidx >> 6, s = tokidx & 63;
    __shared__ float ch[14];
    __shared__ int tok;
    int d = threadIdx.x;
    if (d < 14) ch[d] = board[(size_t)b * 896 + (size_t)d * 64 + s];
    __syncthreads();
    if (d == 0) {
        float mx = ch[0]; int idx = 0;
        #pragma unroll
        for (int c = 1; c < 14; c++) { if (ch[c] > mx) { mx = ch[c]; idx = c; } }
        tok = (mx > 0.0f) ? (idx + 1) : 0;
    }
    __syncthreads();
    float v = emb[tok * DM + d] + pe[s * DM + d];
    size_t o = (size_t)tokidx * DM + d;
    x[o] = v;
    store1(H, E, L, o, v);
}

// ---------------- GEMM: fp16-hi + fp8-correction ----------------
// C[M,N] = A[M,K] @ W[N,K]^T + bias
// D = f16mma(Ah,Wh) + (1/4096)*[f8mma(A8h,W8l) + f8mma(A8l,W8h)]
// 512 threads, tile 128x128, BK=32, warp tile 64x16 (2m x 8n warps).
#define SFH 80u
#define SF8 48u
#define O_AH  0u
#define O_WHS 10240u
#define O_A8H 20480u
#define O_A8L 26624u
#define O_W8H 32768u
#define O_W8L 38912u
#define STG   45056u
#define SMEM_DYN (2u*STG)
#define GM_F32   0
#define GM_RELU  1
#define GM_SPLIT 2

__global__ __launch_bounds__(512, 1) void gemm_x(
    const __half* __restrict__ Ah, const uint8_t* __restrict__ A8h, const uint8_t* __restrict__ A8l,
    const __half* __restrict__ Wh, const uint8_t* __restrict__ W8h, const uint8_t* __restrict__ W8l,
    const float* __restrict__ bias, float* __restrict__ C,
    __half* __restrict__ CH, uint8_t* __restrict__ CE, uint8_t* __restrict__ CL,
    int M, int N, int K, int mode)
{
    extern __shared__ char smdyn[];
    uint32_t su = (uint32_t)__cvta_generic_to_shared(smdyn);
    int tid = threadIdx.x, wid = tid >> 5, lane = tid & 31;
    int grp = lane >> 2, tig = lane & 3;
    int r15 = lane & 15, hseg = lane >> 4;
    int wm = (wid >> 3) * 64, wn = (wid & 7) * 16;
    int bm = blockIdx.y * 128, bn = blockIdx.x * 128;

    float aF[4][2][4], aC[4][2][4];
    #pragma unroll
    for (int i = 0; i < 4; i++)
        #pragma unroll
        for (int j = 0; j < 2; j++)
            #pragma unroll
            for (int r = 0; r < 4; r++) { aF[i][j][r] = 0.0f; aC[i][j][r] = 0.0f; }

    const int nk = K >> 5;

    auto load_stage = [&](int s, int k0) {
        uint32_t b = su + (uint32_t)s * STG;
        {
            int row = tid >> 2, sg = tid & 3;
            cpa16(b + O_AH  + row * SFH + sg * 16, Ah + (size_t)(bm + row) * K + k0 + sg * 8);
            cpa16(b + O_WHS + row * SFH + sg * 16, Wh + (size_t)(bn + row) * K + k0 + sg * 8);
        }
        {
            int t = tid & 255, row = t >> 1, sg = t & 1;
            if (tid < 256) {
                cpa16(b + O_A8H + row * SF8 + sg * 16, A8h + (size_t)(bm + row) * K + k0 + sg * 16);
                cpa16(b + O_W8H + row * SF8 + sg * 16, W8h + (size_t)(bn + row) * K + k0 + sg * 16);
            } else {
                cpa16(b + O_A8L + row * SF8 + sg * 16, A8l + (size_t)(bm + row) * K + k0 + sg * 16);
                cpa16(b + O_W8L + row * SF8 + sg * 16, W8l + (size_t)(bn + row) * K + k0 + sg * 16);
            }
        }
        asm volatile("cp.async.commit_group;" ::: "memory");
    };

    load_stage(0, 0);

    for (int it = 0; it < nk; it++) {
        int s = it & 1;
        if (it + 1 < nk) {
            load_stage(s ^ 1, (it + 1) << 5);
            asm volatile("cp.async.wait_group 1;" ::: "memory");
        } else {
            asm volatile("cp.async.wait_group 0;" ::: "memory");
        }
        __syncthreads();
        uint32_t b = su + (uint32_t)s * STG;

        // fp16 hi*hi
        #pragma unroll
        for (int ks = 0; ks < 2; ks++) {
            uint32_t af[4][4], w0[2], w1[2];
            #pragma unroll
            for (int mf = 0; mf < 4; mf++)
                ldsm4(af[mf][0], af[mf][1], af[mf][2], af[mf][3],
                      b + O_AH + (uint32_t)(wm + mf * 16 + r15) * SFH + ks * 32 + hseg * 16);
            {
                uint32_t t0, t1, t2, t3;
                ldsm4(t0, t1, t2, t3,
                      b + O_WHS + (uint32_t)(wn + r15) * SFH + ks * 32 + hseg * 16);
                w0[0] = t0; w0[1] = t2; w1[0] = t1; w1[1] = t3;
            }
            #pragma unroll
            for (int mf = 0; mf < 4; mf++) {
                mma_f16(aF[mf][0], af[mf], w0);
                mma_f16(aF[mf][1], af[mf], w1);
            }
        }
        // fp8: A8h * W8l
        {
            uint32_t af[4][4], w0[2], w1[2];
            #pragma unroll
            for (int mf = 0; mf < 4; mf++)
                ldsm4(af[mf][0], af[mf][1], af[mf][2], af[mf][3],
                      b + O_A8H + (uint32_t)(wm + mf * 16 + r15) * SF8 + hseg * 16);
            {
                uint32_t t0, t1, t2, t3;
                ldsm4(t0, t1, t2, t3, b + O_W8L + (uint32_t)(wn + r15) * SF8 + hseg * 16);
                w0[0] = t0; w0[1] = t2; w1[0] = t1; w1[1] = t3;
            }
            #pragma unroll
            for (int mf = 0; mf < 4; mf++) {
                mma_f8(aC[mf][0], af[mf], w0);
                mma_f8(aC[mf][1], af[mf], w1);
            }
        }
        // fp8: A8l * W8h
        {
            uint32_t af[4][4], w0[2], w1[2];
            #pragma unroll
            for (int mf = 0; mf < 4; mf++)
                ldsm4(af[mf][0], af[mf][1], af[mf][2], af[mf][3],
                      b + O_A8L + (uint32_t)(wm + mf * 16 + r15) * SF8 + hseg * 16);
            {
                uint32_t t0, t1, t2, t3;
                ldsm4(t0, t1, t2, t3, b + O_W8H + (uint32_t)(wn + r15) * SF8 + hseg * 16);
                w0[0] = t0; w0[1] = t2; w1[0] = t1; w1[1] = t3;
            }
            #pragma unroll
            for (int mf = 0; mf < 4; mf++) {
                mma_f8(aC[mf][0], af[mf], w0);
                mma_f8(aC[mf][1], af[mf], w1);
            }
        }
        __syncthreads();
    }

    const float IS = 1.0f / 4096.0f;
    #pragma unroll
    for (int mf = 0; mf < 4; mf++) {
        int m = bm + wm + mf * 16 + grp;
        #pragma unroll
        for (int nf = 0; nf < 2; nf++) {
            int n = bn + wn + nf * 8 + tig * 2;
            float b0 = bias[n], b1 = bias[n + 1];
            float v0 = aF[mf][nf][0] + aC[mf][nf][0] * IS + b0;
            float v1 = aF[mf][nf][1] + aC[mf][nf][1] * IS + b1;
            float v2 = aF[mf][nf][2] + aC[mf][nf][2] * IS + b0;
            float v3 = aF[mf][nf][3] + aC[mf][nf][3] * IS + b1;
            if (mode != GM_F32) {
                v0 = fmaxf(v0, 0.0f); v1 = fmaxf(v1, 0.0f);
                v2 = fmaxf(v2, 0.0f); v3 = fmaxf(v3, 0.0f);
            }
            size_t o0 = (size_t)m * N + n, o1 = (size_t)(m + 8) * N + n;
            if (mode == GM_SPLIT) {
                store1(CH, CE, CL, o0, v0); store1(CH, CE, CL, o0 + 1, v1);
                store1(CH, CE, CL, o1, v2); store1(CH, CE, CL, o1 + 1, v3);
            } else {
                *(float2*)&C[o0] = make_float2(v0, v1);
                *(float2*)&C[o1] = make_float2(v2, v3);
            }
        }
    }
}

// ---------------- attention ----------------
__global__ __launch_bounds__(256) void attn_kernel(const float* __restrict__ qkv,
                                                   __half* __restrict__ OH,
                                                   uint8_t* __restrict__ OE,
                                                   uint8_t* __restrict__ OL) {
    int bh = blockIdx.x;
    int b = bh >> 3, h = bh & 7;
    __shared__ float qt[32][68];
    __shared__ float kt[32][68];
    __shared__ float vsm[64][36];
    __shared__ float sc[64][68];
    int tid = threadIdx.x;

    #pragma unroll
    for (int t = tid; t < 512; t += 256) {
        int row = t >> 3, dc = (t & 7) << 2;
        size_t base = ((size_t)b * 64 + row) * 768 + h * 32 + dc;
        float4 qv = *(const float4*)&qkv[base];
        float4 kv = *(const float4*)&qkv[base + 256];
        float4 vv = *(const float4*)&qkv[base + 512];
        qt[dc][row] = qv.x; qt[dc + 1][row] = qv.y; qt[dc + 2][row] = qv.z; qt[dc + 3][row] = qv.w;
        kt[dc][row] = kv.x; kt[dc + 1][row] = kv.y; kt[dc + 2][row] = kv.z; kt[dc + 3][row] = kv.w;
        *(float4*)&vsm[row][dc] = vv;
    }
    __syncthreads();
    {
        int i0 = (tid >> 4) << 2, j0 = (tid & 15) << 2;
        float a[4][4];
        #pragma unroll
        for (int ii = 0; ii < 4; ii++)
            #pragma unroll
            for (int jj = 0; jj < 4; jj++) a[ii][jj] = 0.0f;
        #pragma unroll
        for (int d = 0; d < 32; d++) {
            float4 q4 = *(const float4*)&qt[d][i0];
            float4 k4 = *(const float4*)&kt[d][j0];
            float qv[4] = {q4.x, q4.y, q4.z, q4.w};
            float kv[4] = {k4.x, k4.y, k4.z, k4.w};
            #pragma unroll
            for (int ii = 0; ii < 4; ii++)
                #pragma unroll
                for (int jj = 0; jj < 4; jj++)
                    a[ii][jj] = fmaf(qv[ii], kv[jj], a[ii][jj]);
        }
        const float scale = 0.17677669529663687f;
        #pragma unroll
        for (int ii = 0; ii < 4; ii++)
            *(float4*)&sc[i0 + ii][j0] = make_float4(a[ii][0] * scale, a[ii][1] * scale,
                                                     a[ii][2] * scale, a[ii][3] * scale);
    }
    __syncthreads();
    {
        int r = tid >> 2, c0 = (tid & 3) << 4;
        float e[16], mx = -1e30f;
        #pragma unroll
        for (int c = 0; c < 16; c++) { e[c] = sc[r][c0 + c]; mx = fmaxf(mx, e[c]); }
        mx = fmaxf(mx, __shfl_xor_sync(0xffffffffu, mx, 1));
        mx = fmaxf(mx, __shfl_xor_sync(0xffffffffu, mx, 2));
        float sum = 0.0f;
        #pragma unroll
        for (int c = 0; c < 16; c++) { e[c] = __expf(e[c] - mx); sum += e[c]; }
        sum += __shfl_xor_sync(0xffffffffu, sum, 1);
        sum += __shfl_xor_sync(0xffffffffu, sum, 2);
        float inv = 1.0f / sum;
        #pragma unroll
        for (int c = 0; c < 16; c++) sc[r][c0 + c] = e[c] * inv;
    }
    __syncthreads();
    {
        int i0 = (tid >> 3) << 1, d0 = (tid & 7) << 2;
        float a0[4] = {0, 0, 0, 0}, a1[4] = {0, 0, 0, 0};
        #pragma unroll 8
        for (int j = 0; j < 64; j++) {
            float s0 = sc[i0][j], s1 = sc[i0 + 1][j];
            float4 v4 = *(const float4*)&vsm[j][d0];
            float vv[4] = {v4.x, v4.y, v4.z, v4.w};
            #pragma unroll
            for (int dd = 0; dd < 4; dd++) {
                a0[dd] = fmaf(s0, vv[dd], a0[dd]);
                a1[dd] = fmaf(s1, vv[dd], a1[dd]);
            }
        }
        size_t ob = ((size_t)b * 64 + i0) * DM + h * 32 + d0;
        #pragma unroll
        for (int dd = 0; dd < 4; dd++) {
            store1(OH, OE, OL, ob + dd, a0[dd]);
            store1(OH, OE, OL, ob + DM + dd, a1[dd]);
        }
    }
}

// ---------------- residual + LN (+split) ----------------
__global__ __launch_bounds__(256) void add_ln_kernel(float* __restrict__ x,
                                                     const float* __restrict__ y,
                                                     const float* __restrict__ gg,
                                                     const float* __restrict__ bb,
                                                     __half* __restrict__ H,
                                                     uint8_t* __restrict__ E,
                                                     uint8_t* __restrict__ L) {
    size_t base = (size_t)blockIdx.x * 256;
    int d = threadIdx.x;
    float t = x[base + d] + y[base + d];
    __shared__ float red[8];
    __shared__ float stat;
    float s = t;
    #pragma unroll
    for (int off = 16; off; off >>= 1) s += __shfl_xor_sync(0xffffffffu, s, off);
    if ((d & 31) == 0) red[d >> 5] = s;
    __syncthreads();
    if (d == 0) { float m = 0; for (int i = 0; i < 8; i++) m += red[i]; stat = m * (1.0f / 256.0f); }
    __syncthreads();
    float mean = stat;
    float c = t - mean;
    s = c * c;
    #pragma unroll
    for (int off = 16; off; off >>= 1) s += __shfl_xor_sync(0xffffffffu, s, off);
    __syncthreads();
    if ((d & 31) == 0) red[d >> 5] = s;
    __syncthreads();
    if (d == 0) { float v = 0; for (int i = 0; i < 8; i++) v += red[i]; stat = rsqrtf(v * (1.0f / 256.0f) + 1e-5f); }
    __syncthreads();
    float v = c * stat * gg[d] + bb[d];
    x[base + d] = v;
    store1(H, E, L, base + d, v);
}

// ---------------- pool (+split) ----------------
__global__ void pool_kernel(const float* __restrict__ x, __half* __restrict__ H,
                            uint8_t* __restrict__ E, uint8_t* __restrict__ L) {
    int b = blockIdx.x, d = threadIdx.x;
    float s = 0.0f;
    #pragma unroll 8
    for (int i = 0; i < 64; i++) s += x[((size_t)b * 64 + i) * DM + d];
    store1(H, E, L, (size_t)b * DM + d, s * (1.0f / 64.0f));
}

// ---------------- head finals ----------------
__global__ void head_final_kernel(const float* __restrict__ hid, const float* __restrict__ w,
                                  const float* __restrict__ bias, float* __restrict__ out,
                                  int nout, int do_tanh) {
    int b = blockIdx.x, lane = threadIdx.x;
    for (int o = 0; o < nout; o++) {
        float s = 0.0f;
        #pragma unroll
        for (int i = lane; i < 256; i += 32) s = fmaf(hid[(size_t)b * 256 + i], w[o * 256 + i], s);
        #pragma unroll
        for (int off = 16; off; off >>= 1) s += __shfl_xor_sync(0xffffffffu, s, off);
        if (lane == 0) {
            float v = s + bias[o];
            out[(size_t)b * nout + o] = do_tanh ? tanhf(v) : v;
        }
    }
}

// ---------------- host ----------------
struct Trio { __half* h; uint8_t* e; uint8_t* l; };

static inline void gemm(Trio A, Trio W, const float* bias, float* C, Trio Cs,
                        int M, int N, int K, int mode) {
    dim3 g(N / 128, M / 128), blk(512);
    gemm_x<<<g, blk, SMEM_DYN>>>(A.h, A.e, A.l, W.h, W.e, W.l, bias, C, Cs.h, Cs.e, Cs.l,
                                 M, N, K, mode);
}

static inline void split(const float* in, Trio t, size_t n) {
    int n4 = (int)(n / 4);
    split_kernel<<<(n4 + 255) / 256, 256>>>(in, t.h, t.e, t.l, n4);
}

extern "C" void kernel_launch(void* const* d_in, const int* in_sizes, int n_in,
                              void* d_out, int out_size) {
    const float* board = (const float*)d_in[0];
    const float* emb   = (const float*)d_in[1];
    const float* qkv_w = (const float*)d_in[2];
    const float* qkv_b = (const float*)d_in[3];
    const float* out_w = (const float*)d_in[4];
    const float* out_b = (const float*)d_in[5];
    const float* ln1_g = (const float*)d_in[6];
    const float* ln1_b = (const float*)d_in[7];
    const float* ln2_g = (const float*)d_in[8];
    const float* ln2_b = (const float*)d_in[9];
    const float* ff1_w = (const float*)d_in[10];
    const float* ff1_b = (const float*)d_in[11];
    const float* ff2_w = (const float*)d_in[12];
    const float* ff2_b = (const float*)d_in[13];
    const float* vw1 = (const float*)d_in[14];
    const float* vb1 = (const float*)d_in[15];
    const float* vw2 = (const float*)d_in[16];
    const float* vb2 = (const float*)d_in[17];
    const float* pw1 = (const float*)d_in[18];
    const float* pb1 = (const float*)d_in[19];
    const float* pw2 = (const float*)d_in[20];
    const float* pb2 = (const float*)d_in[21];
    const float* cw1 = (const float*)d_in[22];
    const float* cb1 = (const float*)d_in[23];
    const float* cw2 = (const float*)d_in[24];
    const float* cb2 = (const float*)d_in[25];

    float* out = (float*)d_out;
    float* out_value  = out;
    float* out_policy = out + BATCH;
    float* out_class  = out + BATCH + (size_t)BATCH * 4096;

    cudaFuncSetAttribute(gemm_x, cudaFuncAttributeMaxDynamicSharedMemorySize, SMEM_DYN);

    float *px, *pqkv, *py, *ppe, *pvh, *pch;
    cudaGetSymbolAddress((void**)&px,   g_x);
    cudaGetSymbolAddress((void**)&pqkv, g_qkv);
    cudaGetSymbolAddress((void**)&py,   g_y);
    cudaGetSymbolAddress((void**)&ppe,  g_pe);
    cudaGetSymbolAddress((void**)&pvh,  g_vh);
    cudaGetSymbolAddress((void**)&pch,  g_ch);

    Trio X, O, F, H1, P, WP;
    cudaGetSymbolAddress((void**)&X.h,  g_xh);   cudaGetSymbolAddress((void**)&X.e,  g_x8h);
    cudaGetSymbolAddress((void**)&X.l,  g_x8l);
    cudaGetSymbolAddress((void**)&O.h,  g_oh);   cudaGetSymbolAddress((void**)&O.e,  g_o8h);
    cudaGetSymbolAddress((void**)&O.l,  g_o8l);
    cudaGetSymbolAddress((void**)&F.h,  g_fh);   cudaGetSymbolAddress((void**)&F.e,  g_f8h);
    cudaGetSymbolAddress((void**)&F.l,  g_f8l);
    cudaGetSymbolAddress((void**)&H1.h, g_h1h);  cudaGetSymbolAddress((void**)&H1.e, g_h18h);
    cudaGetSymbolAddress((void**)&H1.l, g_h18l);
    cudaGetSymbolAddress((void**)&P.h,  g_ph);   cudaGetSymbolAddress((void**)&P.e,  g_p8h);
    cudaGetSymbolAddress((void**)&P.l,  g_p8l);
    cudaGetSymbolAddress((void**)&WP.h, g_wpH);  cudaGetSymbolAddress((void**)&WP.e, g_wp8h);
    cudaGetSymbolAddress((void**)&WP.l, g_wp8l);

    auto wat = [&](size_t off) { return Trio{WP.h + off, WP.e + off, WP.l + off}; };
    Trio none{0, 0, 0};

    split(qkv_w, wat(OFF_QKV), 6UL * 768 * 256);
    split(out_w, wat(OFF_OUT), 6UL * 256 * 256);
    split(ff1_w, wat(OFF_FF1), 6UL * 1024 * 256);
    split(ff2_w, wat(OFF_FF2), 6UL * 256 * 1024);
    split(vw1,   wat(OFF_VW1), 256UL * 256);
    split(cw1,   wat(OFF_CW1), 256UL * 256);
    split(pw1,   wat(OFF_PW1), 1024UL * 16384);
    split(pw2,   wat(OFF_PW2), 4096UL * 1024);

    pe_kernel<<<SQ, DM>>>(ppe);
    embed_kernel<<<MTOK, DM>>>(board, emb, ppe, px, X.h, X.e, X.l);

    for (int l = 0; l < NL; l++) {
        gemm(X, wat(OFF_QKV + (size_t)l * 768 * 256), qkv_b + (size_t)l * 768,
             pqkv, none, MTOK, 768, 256, GM_F32);
        attn_kernel<<<BATCH * 8, 256>>>(pqkv, O.h, O.e, O.l);
        gemm(O, wat(OFF_OUT + (size_t)l * 256 * 256), out_b + (size_t)l * 256,
             py, none, MTOK, 256, 256, GM_F32);
        add_ln_kernel<<<MTOK, 256>>>(px, py, ln1_g + l * DM, ln1_b + l * DM, X.h, X.e, X.l);
        gemm(X, wat(OFF_FF1 + (size_t)l * 1024 * 256), ff1_b + (size_t)l * 1024,
             0, F, MTOK, 1024, 256, GM_SPLIT);
        gemm(F, wat(OFF_FF2 + (size_t)l * 256 * 1024), ff2_b + (size_t)l * 256,
             py, none, MTOK, 256, 1024, GM_F32);
        add_ln_kernel<<<MTOK, 256>>>(px, py, ln2_g + l * DM, ln2_b + l * DM, X.h, X.e, X.l);
    }

    pool_kernel<<<BATCH, DM>>>(px, P.h, P.e, P.l);

    gemm(P, wat(OFF_VW1), vb1, pvh, none, BATCH, 256, 256, GM_RELU);
    head_final_kernel<<<BATCH, 32>>>(pvh, vw2, vb2, out_value, 1, 1);

    gemm(X, wat(OFF_PW1), pb1, 0, H1, BATCH, 1024, 16384, GM_SPLIT);
    gemm(H1, wat(OFF_PW2), pb2, out_policy, none, BATCH, 4096, 1024, GM_F32);

    gemm(P, wat(OFF_CW1), cb1, pch, none, BATCH, 256, 256, GM_RELU);
    head_final_kernel<<<BATCH, 32>>>(pch, cw2, cb2, out_class, 3, 0);
}

// round 8
// speedup vs baseline: 1.0471x; 1.0471x over previous
#include <cuda_runtime.h>
#include <cuda_fp16.h>
#include <math.h>
#include <stdint.h>

#define BATCH 4096
#define SQ    64
#define DM    256
#define NH    8
#define HDIM  32
#define FFD   1024
#define NL    6
#define MTOK  (BATCH*SQ)   /* 262144 */

// ---------------- scratch (no allocations allowed) ----------------
__device__ float g_x[MTOK*DM];          // activations [B*64, 256]
__device__ float g_qkv[MTOK*3*DM];      // qkv          [B*64, 768]
__device__ float g_o[MTOK*DM];          // attn output
__device__ float g_y[MTOK*DM];          // sublayer output
__device__ float g_ffb[MTOK*FFD];       // ff hidden
__device__ float g_pe[SQ*DM];
__device__ float g_pooled[BATCH*DM];
__device__ float g_vh[BATCH*DM];
__device__ float g_ch[BATCH*DM];
__device__ float g_h1[BATCH*1024];

// ---------------- PE precompute ----------------
__global__ void pe_kernel(float* __restrict__ pe) {
    int s = blockIdx.x, d = threadIdx.x;
    int row = s >> 3, col = s & 7;
    int m = d >> 1;
    float div = powf(10000.0f, (2.0f * (float)m) / 256.0f);
    float v = (d & 1) ? cosf((float)col / div) : sinf((float)row / div);
    pe[s * DM + d] = v;
}

// ---------------- tokens + embedding + PE ----------------
__global__ void embed_kernel(const float* __restrict__ board,
                             const float* __restrict__ emb,
                             const float* __restrict__ pe,
                             float* __restrict__ x) {
    int tokidx = blockIdx.x;          // b*64 + s
    int b = tokidx >> 6, s = tokidx & 63;
    __shared__ float ch[14];
    __shared__ int tok;
    int d = threadIdx.x;              // 256 threads
    if (d < 14) ch[d] = board[(size_t)b * 896 + (size_t)d * 64 + s];
    __syncthreads();
    if (d == 0) {
        float mx = ch[0]; int idx = 0;
        #pragma unroll
        for (int c = 1; c < 14; c++) { if (ch[c] > mx) { mx = ch[c]; idx = c; } }
        tok = (mx > 0.0f) ? (idx + 1) : 0;
    }
    __syncthreads();
    x[(size_t)tokidx * DM + d] = emb[tok * DM + d] + pe[s * DM + d];
}

// ---------------- f16 split helpers ----------------
// x = hi + lo/2048 with hi = f16(x), lo = f16((x - hi)*2048)  (exact pow2 scale)
__device__ __forceinline__ void cvt_split2(float x, float y, uint32_t& hi, uint32_t& lo) {
    __half hx = __float2half(x);
    __half hy = __float2half(y);
    __half lx = __float2half((x - __half2float(hx)) * 2048.0f);
    __half ly = __float2half((y - __half2float(hy)) * 2048.0f);
    hi = ((uint32_t)__half_as_ushort(hy) << 16) | (uint32_t)__half_as_ushort(hx);
    lo = ((uint32_t)__half_as_ushort(ly) << 16) | (uint32_t)__half_as_ushort(lx);
}

// main term: f32 accumulators
__device__ __forceinline__ void mma_f16_f32(float* c, const uint32_t* a, const uint32_t* b) {
    asm volatile(
        "mma.sync.aligned.m16n8k16.row.col.f32.f16.f16.f32 "
        "{%0,%1,%2,%3}, {%4,%5,%6,%7}, {%8,%9}, {%0,%1,%2,%3};\n"
        : "+f"(c[0]), "+f"(c[1]), "+f"(c[2]), "+f"(c[3])
        : "r"(a[0]), "r"(a[1]), "r"(a[2]), "r"(a[3]), "r"(b[0]), "r"(b[1]));
}

// correction terms: f16 accumulators (2x rate if fp32-accum is half-rate)
__device__ __forceinline__ void mma_f16_f16(uint32_t* c, const uint32_t* a, const uint32_t* b) {
    asm volatile(
        "mma.sync.aligned.m16n8k16.row.col.f16.f16.f16.f16 "
        "{%0,%1}, {%2,%3,%4,%5}, {%6,%7}, {%0,%1};\n"
        : "+r"(c[0]), "+r"(c[1])
        : "r"(a[0]), "r"(a[1]), "r"(a[2]), "r"(a[3]), "r"(b[0]), "r"(b[1]));
}

// ---------------- f16-split tensor GEMM: C[M,N] = A[M,K] @ W[N,K]^T + bias (+relu)
// BM=BN=128, BK=32, 512 threads = 16 warps (2m x 8n), warp tile 64x16.
// D = f32mma(Ah,Wh) + (1/2048)*f16acc[ mma(Ah,Wl') + mma(Al',Wh) ]
__global__ __launch_bounds__(512, 1) void gemm_f16c(
    const float* __restrict__ A, const float* __restrict__ W,
    const float* __restrict__ bias, float* __restrict__ C,
    int M, int N, int K, int relu)
{
    // packed f16x2 words along k: word w holds k=2w (lo16) and k=2w+1 (hi16).
    // row stride 20 words (validated conflict-free in round 3).
    __shared__ uint32_t Ah[128][20];
    __shared__ uint32_t Al[128][20];
    __shared__ uint32_t Wh[128][20];
    __shared__ uint32_t Wl[128][20];

    int tid = threadIdx.x;
    int wid = tid >> 5, lane = tid & 31;
    int grp = lane >> 2, tig = lane & 3;
    int wm = (wid >> 3) * 64;       // 0 or 64
    int wn = (wid & 7) * 16;        // 0..112
    int bm = blockIdx.y * 128, bn = blockIdx.x * 128;

    float acc[4][2][4];
    uint32_t cac[4][2][2];
    #pragma unroll
    for (int i = 0; i < 4; i++)
        #pragma unroll
        for (int j = 0; j < 2; j++) {
            #pragma unroll
            for (int r = 0; r < 4; r++) acc[i][j][r] = 0.0f;
            cac[i][j][0] = 0u; cac[i][j][1] = 0u;
        }

    const int ldr = tid >> 3;          // 0..63 row base (+64*i)
    const int ldw = (tid & 7) << 1;    // word col 0,2,..,14

    for (int k0 = 0; k0 < K; k0 += 32) {
        #pragma unroll
        for (int i = 0; i < 2; i++) {
            int row = ldr + 64 * i;    // 0..127
            const float* ap = A + (size_t)(bm + row) * K + k0 + (ldw << 1);
            const float* wp = W + (size_t)(bn + row) * K + k0 + (ldw << 1);
            float4 av = *(const float4*)ap;
            float4 wv = *(const float4*)wp;
            uint32_t h0, l0, h1, l1;
            cvt_split2(av.x, av.y, h0, l0);
            cvt_split2(av.z, av.w, h1, l1);
            *(uint2*)&Ah[row][ldw] = make_uint2(h0, h1);
            *(uint2*)&Al[row][ldw] = make_uint2(l0, l1);
            cvt_split2(wv.x, wv.y, h0, l0);
            cvt_split2(wv.z, wv.w, h1, l1);
            *(uint2*)&Wh[row][ldw] = make_uint2(h0, h1);
            *(uint2*)&Wl[row][ldw] = make_uint2(l0, l1);
        }
        __syncthreads();

        #pragma unroll
        for (int wb = 0; wb < 16; wb += 8) {   // two k16 chunks per BK=32
            uint32_t ah[4][4], al[4][4];
            #pragma unroll
            for (int mf = 0; mf < 4; mf++) {
                int m = wm + mf * 16 + grp;
                ah[mf][0] = Ah[m][wb + tig];
                ah[mf][1] = Ah[m + 8][wb + tig];
                ah[mf][2] = Ah[m][wb + 4 + tig];
                ah[mf][3] = Ah[m + 8][wb + 4 + tig];
                al[mf][0] = Al[m][wb + tig];
                al[mf][1] = Al[m + 8][wb + tig];
                al[mf][2] = Al[m][wb + 4 + tig];
                al[mf][3] = Al[m + 8][wb + 4 + tig];
            }
            #pragma unroll
            for (int nf = 0; nf < 2; nf++) {
                int n = wn + nf * 8 + grp;
                uint32_t bh[2], bl[2];
                bh[0] = Wh[n][wb + tig];
                bh[1] = Wh[n][wb + 4 + tig];
                bl[0] = Wl[n][wb + tig];
                bl[1] = Wl[n][wb + 4 + tig];
                #pragma unroll
                for (int mf = 0; mf < 4; mf++) {
                    mma_f16_f32(acc[mf][nf], ah[mf], bh);   // hi*hi -> f32
                    mma_f16_f16(cac[mf][nf], ah[mf], bl);   // hi*lo' -> f16
                    mma_f16_f16(cac[mf][nf], al[mf], bh);   // lo'*hi -> f16
                }
            }
        }
        __syncthreads();
    }

    const float IS = 1.0f / 2048.0f;
    #pragma unroll
    for (int mf = 0; mf < 4; mf++) {
        int m = bm + wm + mf * 16 + grp;
        #pragma unroll
        for (int nf = 0; nf < 2; nf++) {
            int n = bn + wn + nf * 8 + tig * 2;
            float b0 = bias ? bias[n] : 0.0f;
            float b1 = bias ? bias[n + 1] : 0.0f;
            __half2 p0 = *(__half2*)&cac[mf][nf][0];   // (grp,   n), (grp,   n+1)
            __half2 p1 = *(__half2*)&cac[mf][nf][1];   // (grp+8, n), (grp+8, n+1)
            float v0 = acc[mf][nf][0] + __half2float(__low2half(p0))  * IS + b0;
            float v1 = acc[mf][nf][1] + __half2float(__high2half(p0)) * IS + b1;
            float v2 = acc[mf][nf][2] + __half2float(__low2half(p1))  * IS + b0;
            float v3 = acc[mf][nf][3] + __half2float(__high2half(p1)) * IS + b1;
            if (relu) {
                v0 = fmaxf(v0, 0.0f); v1 = fmaxf(v1, 0.0f);
                v2 = fmaxf(v2, 0.0f); v3 = fmaxf(v3, 0.0f);
            }
            *(float2*)&C[(size_t)m * N + n]       = make_float2(v0, v1);
            *(float2*)&C[(size_t)(m + 8) * N + n] = make_float2(v2, v3);
        }
    }
}

// ---------------- attention: one CTA per (b, h), register-blocked fp32 ----------------
__global__ __launch_bounds__(256) void attn_kernel(const float* __restrict__ qkv,
                                                   float* __restrict__ o) {
    int bh = blockIdx.x;
    int b = bh >> 3, h = bh & 7;
    __shared__ float qt[32][68];   // [d][i] transposed
    __shared__ float kt[32][68];   // [d][j] transposed
    __shared__ float vsm[64][36];  // [j][d]
    __shared__ float sc[64][68];   // [i][j]
    int tid = threadIdx.x;

    #pragma unroll
    for (int t = tid; t < 512; t += 256) {   // 512 float4 per matrix
        int row = t >> 3, dc = (t & 7) << 2;
        size_t base = ((size_t)b * 64 + row) * 768 + h * 32 + dc;
        float4 qv = *(const float4*)&qkv[base];
        float4 kv = *(const float4*)&qkv[base + 256];
        float4 vv = *(const float4*)&qkv[base + 512];
        qt[dc][row] = qv.x; qt[dc + 1][row] = qv.y; qt[dc + 2][row] = qv.z; qt[dc + 3][row] = qv.w;
        kt[dc][row] = kv.x; kt[dc + 1][row] = kv.y; kt[dc + 2][row] = kv.z; kt[dc + 3][row] = kv.w;
        *(float4*)&vsm[row][dc] = vv;
    }
    __syncthreads();

    {
        int i0 = (tid >> 4) << 2;      // 0..60
        int j0 = (tid & 15) << 2;      // 0..60
        float a[4][4];
        #pragma unroll
        for (int ii = 0; ii < 4; ii++)
            #pragma unroll
            for (int jj = 0; jj < 4; jj++) a[ii][jj] = 0.0f;
        #pragma unroll
        for (int d = 0; d < 32; d++) {
            float4 q4 = *(const float4*)&qt[d][i0];
            float4 k4 = *(const float4*)&kt[d][j0];
            float qv[4] = {q4.x, q4.y, q4.z, q4.w};
            float kv[4] = {k4.x, k4.y, k4.z, k4.w};
            #pragma unroll
            for (int ii = 0; ii < 4; ii++)
                #pragma unroll
                for (int jj = 0; jj < 4; jj++)
                    a[ii][jj] = fmaf(qv[ii], kv[jj], a[ii][jj]);
        }
        const float scale = 0.17677669529663687f;  // 1/sqrt(32)
        #pragma unroll
        for (int ii = 0; ii < 4; ii++) {
            *(float4*)&sc[i0 + ii][j0] = make_float4(a[ii][0] * scale, a[ii][1] * scale,
                                                     a[ii][2] * scale, a[ii][3] * scale);
        }
    }
    __syncthreads();

    {
        int r = tid >> 2;
        int c0 = (tid & 3) << 4;
        float e[16];
        float mx = -1e30f;
        #pragma unroll
        for (int c = 0; c < 16; c++) { e[c] = sc[r][c0 + c]; mx = fmaxf(mx, e[c]); }
        mx = fmaxf(mx, __shfl_xor_sync(0xffffffffu, mx, 1));
        mx = fmaxf(mx, __shfl_xor_sync(0xffffffffu, mx, 2));
        float sum = 0.0f;
        #pragma unroll
        for (int c = 0; c < 16; c++) { e[c] = __expf(e[c] - mx); sum += e[c]; }
        sum += __shfl_xor_sync(0xffffffffu, sum, 1);
        sum += __shfl_xor_sync(0xffffffffu, sum, 2);
        float inv = 1.0f / sum;
        #pragma unroll
        for (int c = 0; c < 16; c++) sc[r][c0 + c] = e[c] * inv;
    }
    __syncthreads();

    {
        int i0 = (tid >> 3) << 1;      // 0..62
        int d0 = (tid & 7) << 2;       // 0..28
        float a0[4] = {0, 0, 0, 0}, a1[4] = {0, 0, 0, 0};
        #pragma unroll 8
        for (int j = 0; j < 64; j++) {
            float s0 = sc[i0][j];
            float s1 = sc[i0 + 1][j];
            float4 v4 = *(const float4*)&vsm[j][d0];
            float vv[4] = {v4.x, v4.y, v4.z, v4.w};
            #pragma unroll
            for (int dd = 0; dd < 4; dd++) {
                a0[dd] = fmaf(s0, vv[dd], a0[dd]);
                a1[dd] = fmaf(s1, vv[dd], a1[dd]);
            }
        }
        size_t ob = ((size_t)b * 64 + i0) * DM + h * 32 + d0;
        *(float4*)&o[ob]      = make_float4(a0[0], a0[1], a0[2], a0[3]);
        *(float4*)&o[ob + DM] = make_float4(a1[0], a1[1], a1[2], a1[3]);
    }
}

// ---------------- residual + layernorm (row-wise) ----------------
__global__ __launch_bounds__(256) void add_ln_kernel(float* __restrict__ x,
                                                     const float* __restrict__ y,
                                                     const float* __restrict__ gg,
                                                     const float* __restrict__ bb) {
    size_t base = (size_t)blockIdx.x * 256;
    int d = threadIdx.x;
    float t = x[base + d] + y[base + d];
    __shared__ float red[8];
    __shared__ float stat;
    float s = t;
    #pragma unroll
    for (int off = 16; off; off >>= 1) s += __shfl_xor_sync(0xffffffffu, s, off);
    if ((d & 31) == 0) red[d >> 5] = s;
    __syncthreads();
    if (d == 0) { float m = 0; for (int i = 0; i < 8; i++) m += red[i]; stat = m * (1.0f / 256.0f); }
    __syncthreads();
    float mean = stat;
    float c = t - mean;
    s = c * c;
    #pragma unroll
    for (int off = 16; off; off >>= 1) s += __shfl_xor_sync(0xffffffffu, s, off);
    __syncthreads();
    if ((d & 31) == 0) red[d >> 5] = s;
    __syncthreads();
    if (d == 0) { float v = 0; for (int i = 0; i < 8; i++) v += red[i]; stat = rsqrtf(v * (1.0f / 256.0f) + 1e-5f); }
    __syncthreads();
    x[base + d] = c * stat * gg[d] + bb[d];
}

// ---------------- mean pooling over the 64 squares ----------------
__global__ void pool_kernel(const float* __restrict__ x, float* __restrict__ pooled) {
    int b = blockIdx.x, d = threadIdx.x;
    float s = 0.0f;
    #pragma unroll 8
    for (int i = 0; i < 64; i++) s += x[((size_t)b * 64 + i) * DM + d];
    pooled[(size_t)b * DM + d] = s * (1.0f / 64.0f);
}

// ---------------- tiny head finals (value / classification) ----------------
__global__ void head_final_kernel(const float* __restrict__ hid,
                                  const float* __restrict__ w,
                                  const float* __restrict__ bias,
                                  float* __restrict__ out, int nout, int do_tanh) {
    int b = blockIdx.x;
    int lane = threadIdx.x;  // 32 threads
    for (int o = 0; o < nout; o++) {
        float s = 0.0f;
        #pragma unroll
        for (int i = lane; i < 256; i += 32) s = fmaf(hid[(size_t)b * 256 + i], w[o * 256 + i], s);
        #pragma unroll
        for (int off = 16; off; off >>= 1) s += __shfl_xor_sync(0xffffffffu, s, off);
        if (lane == 0) {
            float v = s + bias[o];
            out[(size_t)b * nout + o] = do_tanh ? tanhf(v) : v;
        }
    }
}

// ---------------- host side ----------------
static inline void sgemm(const float* A, const float* W, const float* bias, float* C,
                         int M, int N, int K, int relu) {
    dim3 g(N / 128, M / 128), blk(512);
    gemm_f16c<<<g, blk>>>(A, W, bias, C, M, N, K, relu);
}

extern "C" void kernel_launch(void* const* d_in, const int* in_sizes, int n_in,
                              void* d_out, int out_size) {
    const float* board = (const float*)d_in[0];
    const float* emb   = (const float*)d_in[1];
    const float* qkv_w = (const float*)d_in[2];
    const float* qkv_b = (const float*)d_in[3];
    const float* out_w = (const float*)d_in[4];
    const float* out_b = (const float*)d_in[5];
    const float* ln1_g = (const float*)d_in[6];
    const float* ln1_b = (const float*)d_in[7];
    const float* ln2_g = (const float*)d_in[8];
    const float* ln2_b = (const float*)d_in[9];
    const float* ff1_w = (const float*)d_in[10];
    const float* ff1_b = (const float*)d_in[11];
    const float* ff2_w = (const float*)d_in[12];
    const float* ff2_b = (const float*)d_in[13];
    const float* vw1 = (const float*)d_in[14];
    const float* vb1 = (const float*)d_in[15];
    const float* vw2 = (const float*)d_in[16];
    const float* vb2 = (const float*)d_in[17];
    const float* pw1 = (const float*)d_in[18];
    const float* pb1 = (const float*)d_in[19];
    const float* pw2 = (const float*)d_in[20];
    const float* pb2 = (const float*)d_in[21];
    const float* cw1 = (const float*)d_in[22];
    const float* cb1 = (const float*)d_in[23];
    const float* cw2 = (const float*)d_in[24];
    const float* cb2 = (const float*)d_in[25];

    float* out = (float*)d_out;
    float* out_value  = out;                                  // [4096, 1]
    float* out_policy = out + BATCH;                          // [4096, 4096]
    float* out_class  = out + BATCH + (size_t)BATCH * 4096;   // [4096, 3]

    float *px, *pqkv, *po, *py, *pff, *ppe, *ppool, *pvh, *pch, *ph1;
    cudaGetSymbolAddress((void**)&px,    g_x);
    cudaGetSymbolAddress((void**)&pqkv,  g_qkv);
    cudaGetSymbolAddress((void**)&po,    g_o);
    cudaGetSymbolAddress((void**)&py,    g_y);
    cudaGetSymbolAddress((void**)&pff,   g_ffb);
    cudaGetSymbolAddress((void**)&ppe,   g_pe);
    cudaGetSymbolAddress((void**)&ppool, g_pooled);
    cudaGetSymbolAddress((void**)&pvh,   g_vh);
    cudaGetSymbolAddress((void**)&pch,   g_ch);
    cudaGetSymbolAddress((void**)&ph1,   g_h1);

    pe_kernel<<<SQ, DM>>>(ppe);
    embed_kernel<<<MTOK, DM>>>(board, emb, ppe, px);

    for (int l = 0; l < NL; l++) {
        const float* Wqkv = qkv_w + (size_t)l * 3 * DM * DM;
        const float* Bqkv = qkv_b + (size_t)l * 3 * DM;
        const float* Wout = out_w + (size_t)l * DM * DM;
        const float* Bout = out_b + (size_t)l * DM;
        const float* W1   = ff1_w + (size_t)l * FFD * DM;
        const float* B1   = ff1_b + (size_t)l * FFD;
        const float* W2   = ff2_w + (size_t)l * DM * FFD;
        const float* B2   = ff2_b + (size_t)l * DM;

        sgemm(px, Wqkv, Bqkv, pqkv, MTOK, 3 * DM, DM, 0);
        attn_kernel<<<BATCH * NH, 256>>>(pqkv, po);
        sgemm(po, Wout, Bout, py, MTOK, DM, DM, 0);
        add_ln_kernel<<<MTOK, 256>>>(px, py, ln1_g + l * DM, ln1_b + l * DM);
        sgemm(px, W1, B1, pff, MTOK, FFD, DM, 1);
        sgemm(pff, W2, B2, py, MTOK, DM, FFD, 0);
        add_ln_kernel<<<MTOK, 256>>>(px, py, ln2_g + l * DM, ln2_b + l * DM);
    }

    // heads
    pool_kernel<<<BATCH, DM>>>(px, ppool);

    sgemm(ppool, vw1, vb1, pvh, BATCH, 256, 256, 1);
    head_final_kernel<<<BATCH, 32>>>(pvh, vw2, vb2, out_value, 1, 1);

    sgemm(px, pw1, pb1, ph1, BATCH, 1024, 16384, 1);      // x viewed as [B, 64*256]
    sgemm(ph1, pw2, pb2, out_policy, BATCH, 4096, 1024, 0);

    sgemm(ppool, cw1, cb1, pch, BATCH, 256, 256, 1);
    head_final_kernel<<<BATCH, 32>>>(pch, cw2, cb2, out_class, 3, 0);
}

// round 9
// speedup vs baseline: 1.5001x; 1.4327x over previous
#include <cuda_runtime.h>
#include <cuda_bf16.h>
#include <cuda_fp16.h>
#include <math.h>
#include <stdint.h>

#define BATCH 4096
#define SQ    64
#define DM    256
#define NH    8
#define FFD   1024
#define NL    6
#define MTOK  (BATCH*SQ)   /* 262144 */

// ---------------- scratch (no allocations allowed) ----------------
__device__ float g_x[MTOK*DM];
__device__ float g_qkv[MTOK*3*DM];
__device__ float g_o[MTOK*DM];
__device__ float g_y[MTOK*DM];
__device__ float g_ffb[MTOK*FFD];
__device__ float g_pe[SQ*DM];
__device__ float g_pooled[BATCH*DM];
__device__ float g_vh[BATCH*DM];
__device__ float g_ch[BATCH*DM];
__device__ float g_h1[BATCH*1024];

// ---------------- PE precompute ----------------
__global__ void pe_kernel(float* __restrict__ pe) {
    int s = blockIdx.x, d = threadIdx.x;
    int row = s >> 3, col = s & 7;
    int m = d >> 1;
    float div = powf(10000.0f, (2.0f * (float)m) / 256.0f);
    float v = (d & 1) ? cosf((float)col / div) : sinf((float)row / div);
    pe[s * DM + d] = v;
}

// ---------------- tokens + embedding + PE ----------------
__global__ void embed_kernel(const float* __restrict__ board,
                             const float* __restrict__ emb,
                             const float* __restrict__ pe,
                             float* __restrict__ x) {
    int tokidx = blockIdx.x;
    int b = tokidx >> 6, s = tokidx & 63;
    __shared__ float ch[14];
    __shared__ int tok;
    int d = threadIdx.x;
    if (d < 14) ch[d] = board[(size_t)b * 896 + (size_t)d * 64 + s];
    __syncthreads();
    if (d == 0) {
        float mx = ch[0]; int idx = 0;
        #pragma unroll
        for (int c = 1; c < 14; c++) { if (ch[c] > mx) { mx = ch[c]; idx = c; } }
        tok = (mx > 0.0f) ? (idx + 1) : 0;
    }
    __syncthreads();
    x[(size_t)tokidx * DM + d] = emb[tok * DM + d] + pe[s * DM + d];
}

// ---------------- bf16 split helpers (GEMM — proven round-3 numerics) ----------------
__device__ __forceinline__ void cvt_split2(float x, float y, uint32_t& hi, uint32_t& lo) {
    __nv_bfloat16 hx = __float2bfloat16(x);
    __nv_bfloat16 hy = __float2bfloat16(y);
    __nv_bfloat16 lx = __float2bfloat16(x - __bfloat162float(hx));
    __nv_bfloat16 ly = __float2bfloat16(y - __bfloat162float(hy));
    hi = ((uint32_t)__bfloat16_as_ushort(hy) << 16) | (uint32_t)__bfloat16_as_ushort(hx);
    lo = ((uint32_t)__bfloat16_as_ushort(ly) << 16) | (uint32_t)__bfloat16_as_ushort(lx);
}

__device__ __forceinline__ void mma_bf16(float* c, const uint32_t* a, const uint32_t* b) {
    asm volatile(
        "mma.sync.aligned.m16n8k16.row.col.f32.bf16.bf16.f32 "
        "{%0,%1,%2,%3}, {%4,%5,%6,%7}, {%8,%9}, {%0,%1,%2,%3};\n"
        : "+f"(c[0]), "+f"(c[1]), "+f"(c[2]), "+f"(c[3])
        : "r"(a[0]), "r"(a[1]), "r"(a[2]), "r"(a[3]), "r"(b[0]), "r"(b[1]));
}

// fp16 mma with f32 accum (attention)
__device__ __forceinline__ void mma_f16(float* c, const uint32_t* a, const uint32_t* b) {
    asm volatile(
        "mma.sync.aligned.m16n8k16.row.col.f32.f16.f16.f32 "
        "{%0,%1,%2,%3}, {%4,%5,%6,%7}, {%8,%9}, {%0,%1,%2,%3};\n"
        : "+f"(c[0]), "+f"(c[1]), "+f"(c[2]), "+f"(c[3])
        : "r"(a[0]), "r"(a[1]), "r"(a[2]), "r"(a[3]), "r"(b[0]), "r"(b[1]));
}

__device__ __forceinline__ uint32_t packh(float a, float b) {
    __half2 t = __floats2half2_rn(a, b);     // .x = a (low half)
    return *(uint32_t*)&t;
}

__device__ __forceinline__ void cvt_split2_f16(float x, float y, uint32_t& hi, uint32_t& lo) {
    __half hx = __float2half(x);
    __half hy = __float2half(y);
    hi = ((uint32_t)__half_as_ushort(hy) << 16) | (uint32_t)__half_as_ushort(hx);
    lo = packh(x - __half2float(hx), y - __half2float(hy));
}

// ---------------- bf16x3 tensor GEMM (EXACT round-3 kernel, 36.7ms proven) ----------
__global__ __launch_bounds__(256, 2) void gemm_bf16x2(
    const float* __restrict__ A, const float* __restrict__ W,
    const float* __restrict__ bias, float* __restrict__ C,
    int M, int N, int K, int relu)
{
    __shared__ uint32_t Ah[128][20];
    __shared__ uint32_t Al[128][20];
    __shared__ uint32_t Wh[128][20];
    __shared__ uint32_t Wl[128][20];

    int tid = threadIdx.x;
    int wid = tid >> 5, lane = tid & 31;
    int grp = lane >> 2, tig = lane & 3;
    int wm = (wid >> 2) * 64;
    int wn = (wid & 3) * 32;
    int bm = blockIdx.y * 128, bn = blockIdx.x * 128;

    float acc[4][4][4];
    #pragma unroll
    for (int i = 0; i < 4; i++)
        #pragma unroll
        for (int j = 0; j < 4; j++)
            #pragma unroll
            for (int r = 0; r < 4; r++) acc[i][j][r] = 0.0f;

    const int ldr = tid >> 3;
    const int ldw = (tid & 7) << 1;

    for (int k0 = 0; k0 < K; k0 += 32) {
        #pragma unroll
        for (int i = 0; i < 4; i++) {
            int row = ldr + 32 * i;
            const float* ap = A + (size_t)(bm + row) * K + k0 + (ldw << 1);
            const float* wp = W + (size_t)(bn + row) * K + k0 + (ldw << 1);
            float4 av = *(const float4*)ap;
            float4 wv = *(const float4*)wp;
            uint32_t h0, l0, h1, l1;
            cvt_split2(av.x, av.y, h0, l0);
            cvt_split2(av.z, av.w, h1, l1);
            *(uint2*)&Ah[row][ldw] = make_uint2(h0, h1);
            *(uint2*)&Al[row][ldw] = make_uint2(l0, l1);
            cvt_split2(wv.x, wv.y, h0, l0);
            cvt_split2(wv.z, wv.w, h1, l1);
            *(uint2*)&Wh[row][ldw] = make_uint2(h0, h1);
            *(uint2*)&Wl[row][ldw] = make_uint2(l0, l1);
        }
        __syncthreads();

        #pragma unroll
        for (int wb = 0; wb < 16; wb += 8) {
            uint32_t ah[4][4], al[4][4];
            #pragma unroll
            for (int mf = 0; mf < 4; mf++) {
                int m = wm + mf * 16 + grp;
                ah[mf][0] = Ah[m][wb + tig];
                ah[mf][1] = Ah[m + 8][wb + tig];
                ah[mf][2] = Ah[m][wb + 4 + tig];
                ah[mf][3] = Ah[m + 8][wb + 4 + tig];
                al[mf][0] = Al[m][wb + tig];
                al[mf][1] = Al[m + 8][wb + tig];
                al[mf][2] = Al[m][wb + 4 + tig];
                al[mf][3] = Al[m + 8][wb + 4 + tig];
            }
            #pragma unroll
            for (int nf = 0; nf < 4; nf++) {
                int n = wn + nf * 8 + grp;
                uint32_t bh[2], bl[2];
                bh[0] = Wh[n][wb + tig];
                bh[1] = Wh[n][wb + 4 + tig];
                bl[0] = Wl[n][wb + tig];
                bl[1] = Wl[n][wb + 4 + tig];
                #pragma unroll
                for (int mf = 0; mf < 4; mf++) {
                    mma_bf16(acc[mf][nf], ah[mf], bh);
                    mma_bf16(acc[mf][nf], ah[mf], bl);
                    mma_bf16(acc[mf][nf], al[mf], bh);
                }
            }
        }
        __syncthreads();
    }

    #pragma unroll
    for (int mf = 0; mf < 4; mf++) {
        int m = bm + wm + mf * 16 + grp;
        #pragma unroll
        for (int nf = 0; nf < 4; nf++) {
            int n = bn + wn + nf * 8 + tig * 2;
            float b0 = bias ? bias[n] : 0.0f;
            float b1 = bias ? bias[n + 1] : 0.0f;
            float v0 = acc[mf][nf][0] + b0;
            float v1 = acc[mf][nf][1] + b1;
            float v2 = acc[mf][nf][2] + b0;
            float v3 = acc[mf][nf][3] + b1;
            if (relu) {
                v0 = fmaxf(v0, 0.0f); v1 = fmaxf(v1, 0.0f);
                v2 = fmaxf(v2, 0.0f); v3 = fmaxf(v3, 0.0f);
            }
            *(float2*)&C[(size_t)m * N + n]       = make_float2(v0, v1);
            *(float2*)&C[(size_t)(m + 8) * N + n] = make_float2(v2, v3);
        }
    }
}

// ---------------- tensor-core attention: one CTA per board, one warp per head --------
// QK^T: q,k fp16-split 3-term. softmax in registers. AV: P fp16-split 2-term, V fp16.
// smem word layout: QH 0, QL 10240, KH 20480, KL 30720 (each head 64x20 words),
//                   VH 40960 (each head 32x36 words, V transposed [d][j] halves)
#define AQH 0u
#define AQL 10240u
#define AKH 20480u
#define AKL 30720u
#define AVH 40960u
#define ATTN_SMEM (50176u * 4u)   /* 200704 B */

__global__ __launch_bounds__(256, 1) void attn_mma_kernel(const float* __restrict__ qkv,
                                                          float* __restrict__ o) {
    extern __shared__ uint32_t smw[];
    int b = blockIdx.x;
    int tid = threadIdx.x;
    int wid = tid >> 5, lane = tid & 31;
    int grp = lane >> 2, tig = lane & 3;

    const float scale = 0.17677669529663687f;   // 1/sqrt(32), folded into q

    // ---- cooperative load: q,k split fp16; v transposed single fp16 ----
    #pragma unroll
    for (int it = 0; it < 16; it++) {
        int idx = it * 256 + tid;                // 0..4095
        int h = idx >> 9;                        // 512 float4 per head
        int r = (idx >> 3) & 63;
        int j4 = idx & 7;                        // d0 = j4*4
        size_t base = ((size_t)b * 64 + r) * 768 + h * 32 + j4 * 4;
        float4 qv = *(const float4*)&qkv[base];
        float4 kv = *(const float4*)&qkv[base + 256];
        float4 vv = *(const float4*)&qkv[base + 512];
        qv.x *= scale; qv.y *= scale; qv.z *= scale; qv.w *= scale;
        uint32_t h0, l0, h1, l1;
        int qb = h * 1280 + r * 20 + j4 * 2;
        cvt_split2_f16(qv.x, qv.y, h0, l0);
        cvt_split2_f16(qv.z, qv.w, h1, l1);
        smw[AQH + qb] = h0; smw[AQH + qb + 1] = h1;
        smw[AQL + qb] = l0; smw[AQL + qb + 1] = l1;
        cvt_split2_f16(kv.x, kv.y, h0, l0);
        cvt_split2_f16(kv.z, kv.w, h1, l1);
        smw[AKH + qb] = h0; smw[AKH + qb + 1] = h1;
        smw[AKL + qb] = l0; smw[AKL + qb + 1] = l1;
        __half* vp = (__half*)(smw + AVH) + h * 2304;   // 1152 words/head = 2304 halves
        vp[(j4 * 4 + 0) * 72 + r] = __float2half(vv.x);
        vp[(j4 * 4 + 1) * 72 + r] = __float2half(vv.y);
        vp[(j4 * 4 + 2) * 72 + r] = __float2half(vv.z);
        vp[(j4 * 4 + 3) * 72 + r] = __float2half(vv.w);
    }
    __syncthreads();

    // ---- per-warp head ----
    int h = wid;
    const uint32_t qh0 = AQH + h * 1280, ql0 = AQL + h * 1280;
    const uint32_t kh0 = AKH + h * 1280, kl0 = AKL + h * 1280;
    const uint32_t vh0 = AVH + h * 1152;

    float O[4][4][4];
    #pragma unroll
    for (int i = 0; i < 4; i++)
        #pragma unroll
        for (int j = 0; j < 4; j++)
            #pragma unroll
            for (int r = 0; r < 4; r++) O[i][j][r] = 0.0f;

    #pragma unroll
    for (int mf = 0; mf < 4; mf++) {
        float S[8][4];
        #pragma unroll
        for (int nf = 0; nf < 8; nf++)
            #pragma unroll
            for (int r = 0; r < 4; r++) S[nf][r] = 0.0f;

        // QK^T 3-term over d=32 (2 k16 chunks)
        #pragma unroll
        for (int kc = 0; kc < 2; kc++) {
            int rA = mf * 16 + grp;
            uint32_t ah[4], al[4];
            ah[0] = smw[qh0 + rA * 20 + kc * 8 + tig];
            ah[1] = smw[qh0 + (rA + 8) * 20 + kc * 8 + tig];
            ah[2] = smw[qh0 + rA * 20 + kc * 8 + 4 + tig];
            ah[3] = smw[qh0 + (rA + 8) * 20 + kc * 8 + 4 + tig];
            al[0] = smw[ql0 + rA * 20 + kc * 8 + tig];
            al[1] = smw[ql0 + (rA + 8) * 20 + kc * 8 + tig];
            al[2] = smw[ql0 + rA * 20 + kc * 8 + 4 + tig];
            al[3] = smw[ql0 + (rA + 8) * 20 + kc * 8 + 4 + tig];
            #pragma unroll
            for (int nf = 0; nf < 8; nf++) {
                int rB = nf * 8 + grp;
                uint32_t bh[2], bl[2];
                bh[0] = smw[kh0 + rB * 20 + kc * 8 + tig];
                bh[1] = smw[kh0 + rB * 20 + kc * 8 + 4 + tig];
                bl[0] = smw[kl0 + rB * 20 + kc * 8 + tig];
                bl[1] = smw[kl0 + rB * 20 + kc * 8 + 4 + tig];
                mma_f16(S[nf], ah, bh);
                mma_f16(S[nf], ah, bl);
                mma_f16(S[nf], al, bh);
            }
        }

        // softmax: rows (mf*16+grp) and (mf*16+grp+8); cols split over 4-lane shfl group
        float m0 = -1e30f, m1 = -1e30f;
        #pragma unroll
        for (int nf = 0; nf < 8; nf++) {
            m0 = fmaxf(m0, fmaxf(S[nf][0], S[nf][1]));
            m1 = fmaxf(m1, fmaxf(S[nf][2], S[nf][3]));
        }
        m0 = fmaxf(m0, __shfl_xor_sync(0xffffffffu, m0, 1));
        m0 = fmaxf(m0, __shfl_xor_sync(0xffffffffu, m0, 2));
        m1 = fmaxf(m1, __shfl_xor_sync(0xffffffffu, m1, 1));
        m1 = fmaxf(m1, __shfl_xor_sync(0xffffffffu, m1, 2));
        float s0 = 0.0f, s1 = 0.0f;
        #pragma unroll
        for (int nf = 0; nf < 8; nf++) {
            S[nf][0] = __expf(S[nf][0] - m0); s0 += S[nf][0];
            S[nf][1] = __expf(S[nf][1] - m0); s0 += S[nf][1];
            S[nf][2] = __expf(S[nf][2] - m1); s1 += S[nf][2];
            S[nf][3] = __expf(S[nf][3] - m1); s1 += S[nf][3];
        }
        s0 += __shfl_xor_sync(0xffffffffu, s0, 1);
        s0 += __shfl_xor_sync(0xffffffffu, s0, 2);
        s1 += __shfl_xor_sync(0xffffffffu, s1, 1);
        s1 += __shfl_xor_sync(0xffffffffu, s1, 2);
        float i0 = 1.0f / s0, i1 = 1.0f / s1;

        // P fragments: ph (fp16) + pl (residual), packed per n-frag
        uint32_t PHa[8], PHb[8], PLa[8], PLb[8];
        #pragma unroll
        for (int nf = 0; nf < 8; nf++) {
            float p0 = S[nf][0] * i0, p1 = S[nf][1] * i0;
            float p2 = S[nf][2] * i1, p3 = S[nf][3] * i1;
            uint32_t ph = packh(p0, p1);
            __half2 hv = *(__half2*)&ph;
            PHa[nf] = ph;
            PLa[nf] = packh(p0 - __half2float(hv.x), p1 - __half2float(hv.y));
            ph = packh(p2, p3);
            hv = *(__half2*)&ph;
            PHb[nf] = ph;
            PLb[nf] = packh(p2 - __half2float(hv.x), p3 - __half2float(hv.y));
        }

        // AV: O[mf] += P * V, 2-term (ph + pl), V single fp16
        #pragma unroll
        for (int jc = 0; jc < 4; jc++) {
            uint32_t aph[4] = { PHa[2 * jc], PHb[2 * jc], PHa[2 * jc + 1], PHb[2 * jc + 1] };
            uint32_t apl[4] = { PLa[2 * jc], PLb[2 * jc], PLa[2 * jc + 1], PLb[2 * jc + 1] };
            #pragma unroll
            for (int no = 0; no < 4; no++) {
                int rB = no * 8 + grp;
                uint32_t bv[2];
                bv[0] = smw[vh0 + rB * 36 + jc * 8 + tig];
                bv[1] = smw[vh0 + rB * 36 + jc * 8 + 4 + tig];
                mma_f16(O[mf][no], aph, bv);
                mma_f16(O[mf][no], apl, bv);
            }
        }
    }

    // ---- epilogue ----
    #pragma unroll
    for (int mf = 0; mf < 4; mf++) {
        int row = mf * 16 + grp;
        #pragma unroll
        for (int no = 0; no < 4; no++) {
            int d = no * 8 + tig * 2;
            size_t ob = ((size_t)b * 64 + row) * DM + h * 32 + d;
            *(float2*)&o[ob]            = make_float2(O[mf][no][0], O[mf][no][1]);
            *(float2*)&o[ob + 8 * DM]   = make_float2(O[mf][no][2], O[mf][no][3]);
        }
    }
}

// ---------------- residual + layernorm: warp per row, 8 rows per block --------------
__global__ __launch_bounds__(256) void add_ln_kernel(float* __restrict__ x,
                                                     const float* __restrict__ y,
                                                     const float* __restrict__ gg,
                                                     const float* __restrict__ bb) {
    int wid = threadIdx.x >> 5, lane = threadIdx.x & 31;
    size_t base = ((size_t)blockIdx.x * 8 + wid) * 256;
    int c0 = lane * 4, c1 = 128 + lane * 4;
    float4 a0 = *(const float4*)&x[base + c0];
    float4 b0 = *(const float4*)&y[base + c0];
    float4 a1 = *(const float4*)&x[base + c1];
    float4 b1 = *(const float4*)&y[base + c1];
    float t[8] = { a0.x + b0.x, a0.y + b0.y, a0.z + b0.z, a0.w + b0.w,
                   a1.x + b1.x, a1.y + b1.y, a1.z + b1.z, a1.w + b1.w };
    float s = 0.0f;
    #pragma unroll
    for (int i = 0; i < 8; i++) s += t[i];
    #pragma unroll
    for (int off = 16; off; off >>= 1) s += __shfl_xor_sync(0xffffffffu, s, off);
    float mean = s * (1.0f / 256.0f);
    float v = 0.0f;
    #pragma unroll
    for (int i = 0; i < 8; i++) { t[i] -= mean; v += t[i] * t[i]; }
    #pragma unroll
    for (int off = 16; off; off >>= 1) v += __shfl_xor_sync(0xffffffffu, v, off);
    float rstd = rsqrtf(v * (1.0f / 256.0f) + 1e-5f);
    float4 g0 = *(const float4*)&gg[c0];
    float4 g1 = *(const float4*)&gg[c1];
    float4 e0 = *(const float4*)&bb[c0];
    float4 e1 = *(const float4*)&bb[c1];
    float4 r0 = make_float4(t[0] * rstd * g0.x + e0.x, t[1] * rstd * g0.y + e0.y,
                            t[2] * rstd * g0.z + e0.z, t[3] * rstd * g0.w + e0.w);
    float4 r1 = make_float4(t[4] * rstd * g1.x + e1.x, t[5] * rstd * g1.y + e1.y,
                            t[6] * rstd * g1.z + e1.z, t[7] * rstd * g1.w + e1.w);
    *(float4*)&x[base + c0] = r0;
    *(float4*)&x[base + c1] = r1;
}

// ---------------- mean pooling ----------------
__global__ void pool_kernel(const float* __restrict__ x, float* __restrict__ pooled) {
    int b = blockIdx.x, d = threadIdx.x;
    float s = 0.0f;
    #pragma unroll 8
    for (int i = 0; i < 64; i++) s += x[((size_t)b * 64 + i) * DM + d];
    pooled[(size_t)b * DM + d] = s * (1.0f / 64.0f);
}

// ---------------- tiny head finals ----------------
__global__ void head_final_kernel(const float* __restrict__ hid,
                                  const float* __restrict__ w,
                                  const float* __restrict__ bias,
                                  float* __restrict__ out, int nout, int do_tanh) {
    int b = blockIdx.x;
    int lane = threadIdx.x;
    for (int o = 0; o < nout; o++) {
        float s = 0.0f;
        #pragma unroll
        for (int i = lane; i < 256; i += 32) s = fmaf(hid[(size_t)b * 256 + i], w[o * 256 + i], s);
        #pragma unroll
        for (int off = 16; off; off >>= 1) s += __shfl_xor_sync(0xffffffffu, s, off);
        if (lane == 0) {
            float v = s + bias[o];
            out[(size_t)b * nout + o] = do_tanh ? tanhf(v) : v;
        }
    }
}

// ---------------- host side ----------------
static inline void sgemm(const float* A, const float* W, const float* bias, float* C,
                         int M, int N, int K, int relu) {
    dim3 g(N / 128, M / 128), blk(256);
    gemm_bf16x2<<<g, blk>>>(A, W, bias, C, M, N, K, relu);
}

extern "C" void kernel_launch(void* const* d_in, const int* in_sizes, int n_in,
                              void* d_out, int out_size) {
    const float* board = (const float*)d_in[0];
    const float* emb   = (const float*)d_in[1];
    const float* qkv_w = (const float*)d_in[2];
    const float* qkv_b = (const float*)d_in[3];
    const float* out_w = (const float*)d_in[4];
    const float* out_b = (const float*)d_in[5];
    const float* ln1_g = (const float*)d_in[6];
    const float* ln1_b = (const float*)d_in[7];
    const float* ln2_g = (const float*)d_in[8];
    const float* ln2_b = (const float*)d_in[9];
    const float* ff1_w = (const float*)d_in[10];
    const float* ff1_b = (const float*)d_in[11];
    const float* ff2_w = (const float*)d_in[12];
    const float* ff2_b = (const float*)d_in[13];
    const float* vw1 = (const float*)d_in[14];
    const float* vb1 = (const float*)d_in[15];
    const float* vw2 = (const float*)d_in[16];
    const float* vb2 = (const float*)d_in[17];
    const float* pw1 = (const float*)d_in[18];
    const float* pb1 = (const float*)d_in[19];
    const float* pw2 = (const float*)d_in[20];
    const float* pb2 = (const float*)d_in[21];
    const float* cw1 = (const float*)d_in[22];
    const float* cb1 = (const float*)d_in[23];
    const float* cw2 = (const float*)d_in[24];
    const float* cb2 = (const float*)d_in[25];

    float* out = (float*)d_out;
    float* out_value  = out;
    float* out_policy = out + BATCH;
    float* out_class  = out + BATCH + (size_t)BATCH * 4096;

    cudaFuncSetAttribute(attn_mma_kernel, cudaFuncAttributeMaxDynamicSharedMemorySize,
                         ATTN_SMEM);

    float *px, *pqkv, *po, *py, *pff, *ppe, *ppool, *pvh, *pch, *ph1;
    cudaGetSymbolAddress((void**)&px,    g_x);
    cudaGetSymbolAddress((void**)&pqkv,  g_qkv);
    cudaGetSymbolAddress((void**)&po,    g_o);
    cudaGetSymbolAddress((void**)&py,    g_y);
    cudaGetSymbolAddress((void**)&pff,   g_ffb);
    cudaGetSymbolAddress((void**)&ppe,   g_pe);
    cudaGetSymbolAddress((void**)&ppool, g_pooled);
    cudaGetSymbolAddress((void**)&pvh,   g_vh);
    cudaGetSymbolAddress((void**)&pch,   g_ch);
    cudaGetSymbolAddress((void**)&ph1,   g_h1);

    pe_kernel<<<SQ, DM>>>(ppe);
    embed_kernel<<<MTOK, DM>>>(board, emb, ppe, px);

    for (int l = 0; l < NL; l++) {
        const float* Wqkv = qkv_w + (size_t)l * 3 * DM * DM;
        const float* Bqkv = qkv_b + (size_t)l * 3 * DM;
        const float* Wout = out_w + (size_t)l * DM * DM;
        const float* Bout = out_b + (size_t)l * DM;
        const float* W1   = ff1_w + (size_t)l * FFD * DM;
        const float* B1   = ff1_b + (size_t)l * FFD;
        const float* W2   = ff2_w + (size_t)l * DM * FFD;
        const float* B2   = ff2_b + (size_t)l * DM;

        sgemm(px, Wqkv, Bqkv, pqkv, MTOK, 3 * DM, DM, 0);
        attn_mma_kernel<<<BATCH, 256, ATTN_SMEM>>>(pqkv, po);
        sgemm(po, Wout, Bout, py, MTOK, DM, DM, 0);
        add_ln_kernel<<<MTOK / 8, 256>>>(px, py, ln1_g + l * DM, ln1_b + l * DM);
        sgemm(px, W1, B1, pff, MTOK, FFD, DM, 1);
        sgemm(pff, W2, B2, py, MTOK, DM, FFD, 0);
        add_ln_kernel<<<MTOK / 8, 256>>>(px, py, ln2_g + l * DM, ln2_b + l * DM);
    }

    // heads
    pool_kernel<<<BATCH, DM>>>(px, ppool);

    sgemm(ppool, vw1, vb1, pvh, BATCH, 256, 256, 1);
    head_final_kernel<<<BATCH, 32>>>(pvh, vw2, vb2, out_value, 1, 1);

    sgemm(px, pw1, pb1, ph1, BATCH, 1024, 16384, 1);      // x viewed as [B, 64*256]
    sgemm(ph1, pw2, pb2, out_policy, BATCH, 4096, 1024, 0);

    sgemm(ppool, cw1, cb1, pch, BATCH, 256, 256, 1);
    head_final_kernel<<<BATCH, 32>>>(pch, cw2, cb2, out_class, 3, 0);
}

// round 10
// speedup vs baseline: 1.5629x; 1.0419x over previous
#include <cuda_runtime.h>
#include <cuda_bf16.h>
#include <cuda_fp16.h>
#include <math.h>
#include <stdint.h>

#define BATCH 4096
#define SQ    64
#define DM    256
#define NH    8
#define FFD   1024
#define NL    6
#define MTOK  (BATCH*SQ)   /* 262144 */

// ---------------- scratch (no allocations allowed) ----------------
__device__ float g_x[MTOK*DM];
__device__ float g_qkv[MTOK*3*DM];
__device__ float g_o[MTOK*DM];
__device__ float g_y[MTOK*DM];
__device__ float g_ffb[MTOK*FFD];
__device__ float g_pe[SQ*DM];
__device__ float g_pooled[BATCH*DM];
__device__ float g_vh[BATCH*DM];
__device__ float g_ch[BATCH*DM];
__device__ float g_h1[BATCH*1024];

// ---------------- PE precompute ----------------
__global__ void pe_kernel(float* __restrict__ pe) {
    int s = blockIdx.x, d = threadIdx.x;
    int row = s >> 3, col = s & 7;
    int m = d >> 1;
    float div = powf(10000.0f, (2.0f * (float)m) / 256.0f);
    float v = (d & 1) ? cosf((float)col / div) : sinf((float)row / div);
    pe[s * DM + d] = v;
}

// ---------------- tokens + embedding + PE ----------------
__global__ void embed_kernel(const float* __restrict__ board,
                             const float* __restrict__ emb,
                             const float* __restrict__ pe,
                             float* __restrict__ x) {
    int tokidx = blockIdx.x;
    int b = tokidx >> 6, s = tokidx & 63;
    __shared__ float ch[14];
    __shared__ int tok;
    int d = threadIdx.x;
    if (d < 14) ch[d] = board[(size_t)b * 896 + (size_t)d * 64 + s];
    __syncthreads();
    if (d == 0) {
        float mx = ch[0]; int idx = 0;
        #pragma unroll
        for (int c = 1; c < 14; c++) { if (ch[c] > mx) { mx = ch[c]; idx = c; } }
        tok = (mx > 0.0f) ? (idx + 1) : 0;
    }
    __syncthreads();
    x[(size_t)tokidx * DM + d] = emb[tok * DM + d] + pe[s * DM + d];
}

// ---------------- bf16 split helpers (GEMM — proven numerics) ----------------
__device__ __forceinline__ void cvt_split2(float x, float y, uint32_t& hi, uint32_t& lo) {
    __nv_bfloat16 hx = __float2bfloat16(x);
    __nv_bfloat16 hy = __float2bfloat16(y);
    __nv_bfloat16 lx = __float2bfloat16(x - __bfloat162float(hx));
    __nv_bfloat16 ly = __float2bfloat16(y - __bfloat162float(hy));
    hi = ((uint32_t)__bfloat16_as_ushort(hy) << 16) | (uint32_t)__bfloat16_as_ushort(hx);
    lo = ((uint32_t)__bfloat16_as_ushort(ly) << 16) | (uint32_t)__bfloat16_as_ushort(lx);
}

__device__ __forceinline__ void mma_bf16(float* c, const uint32_t* a, const uint32_t* b) {
    asm volatile(
        "mma.sync.aligned.m16n8k16.row.col.f32.bf16.bf16.f32 "
        "{%0,%1,%2,%3}, {%4,%5,%6,%7}, {%8,%9}, {%0,%1,%2,%3};\n"
        : "+f"(c[0]), "+f"(c[1]), "+f"(c[2]), "+f"(c[3])
        : "r"(a[0]), "r"(a[1]), "r"(a[2]), "r"(a[3]), "r"(b[0]), "r"(b[1]));
}

__device__ __forceinline__ void mma_f16(float* c, const uint32_t* a, const uint32_t* b) {
    asm volatile(
        "mma.sync.aligned.m16n8k16.row.col.f32.f16.f16.f32 "
        "{%0,%1,%2,%3}, {%4,%5,%6,%7}, {%8,%9}, {%0,%1,%2,%3};\n"
        : "+f"(c[0]), "+f"(c[1]), "+f"(c[2]), "+f"(c[3])
        : "r"(a[0]), "r"(a[1]), "r"(a[2]), "r"(a[3]), "r"(b[0]), "r"(b[1]));
}

__device__ __forceinline__ uint32_t packh(float a, float b) {
    __half2 t = __floats2half2_rn(a, b);
    return *(uint32_t*)&t;
}

__device__ __forceinline__ void cvt_split2_f16(float x, float y, uint32_t& hi, uint32_t& lo) {
    __half hx = __float2half(x);
    __half hy = __float2half(y);
    hi = ((uint32_t)__half_as_ushort(hy) << 16) | (uint32_t)__half_as_ushort(hx);
    lo = packh(x - __half2float(hx), y - __half2float(hy));
}

// ---------------- bf16x3 tensor GEMM (proven mainloop; epilogue gains +RES) --------
__global__ __launch_bounds__(256, 2) void gemm_bf16x2(
    const float* __restrict__ A, const float* __restrict__ W,
    const float* __restrict__ bias, const float* __restrict__ RES,
    float* __restrict__ C, int M, int N, int K, int relu)
{
    __shared__ uint32_t Ah[128][20];
    __shared__ uint32_t Al[128][20];
    __shared__ uint32_t Wh[128][20];
    __shared__ uint32_t Wl[128][20];

    int tid = threadIdx.x;
    int wid = tid >> 5, lane = tid & 31;
    int grp = lane >> 2, tig = lane & 3;
    int wm = (wid >> 2) * 64;
    int wn = (wid & 3) * 32;
    int bm = blockIdx.y * 128, bn = blockIdx.x * 128;

    float acc[4][4][4];
    #pragma unroll
    for (int i = 0; i < 4; i++)
        #pragma unroll
        for (int j = 0; j < 4; j++)
            #pragma unroll
            for (int r = 0; r < 4; r++) acc[i][j][r] = 0.0f;

    const int ldr = tid >> 3;
    const int ldw = (tid & 7) << 1;

    for (int k0 = 0; k0 < K; k0 += 32) {
        #pragma unroll
        for (int i = 0; i < 4; i++) {
            int row = ldr + 32 * i;
            const float* ap = A + (size_t)(bm + row) * K + k0 + (ldw << 1);
            const float* wp = W + (size_t)(bn + row) * K + k0 + (ldw << 1);
            float4 av = *(const float4*)ap;
            float4 wv = *(const float4*)wp;
            uint32_t h0, l0, h1, l1;
            cvt_split2(av.x, av.y, h0, l0);
            cvt_split2(av.z, av.w, h1, l1);
            *(uint2*)&Ah[row][ldw] = make_uint2(h0, h1);
            *(uint2*)&Al[row][ldw] = make_uint2(l0, l1);
            cvt_split2(wv.x, wv.y, h0, l0);
            cvt_split2(wv.z, wv.w, h1, l1);
            *(uint2*)&Wh[row][ldw] = make_uint2(h0, h1);
            *(uint2*)&Wl[row][ldw] = make_uint2(l0, l1);
        }
        __syncthreads();

        #pragma unroll
        for (int wb = 0; wb < 16; wb += 8) {
            uint32_t ah[4][4], al[4][4];
            #pragma unroll
            for (int mf = 0; mf < 4; mf++) {
                int m = wm + mf * 16 + grp;
                ah[mf][0] = Ah[m][wb + tig];
                ah[mf][1] = Ah[m + 8][wb + tig];
                ah[mf][2] = Ah[m][wb + 4 + tig];
                ah[mf][3] = Ah[m + 8][wb + 4 + tig];
                al[mf][0] = Al[m][wb + tig];
                al[mf][1] = Al[m + 8][wb + tig];
                al[mf][2] = Al[m][wb + 4 + tig];
                al[mf][3] = Al[m + 8][wb + 4 + tig];
            }
            #pragma unroll
            for (int nf = 0; nf < 4; nf++) {
                int n = wn + nf * 8 + grp;
                uint32_t bh[2], bl[2];
                bh[0] = Wh[n][wb + tig];
                bh[1] = Wh[n][wb + 4 + tig];
                bl[0] = Wl[n][wb + tig];
                bl[1] = Wl[n][wb + 4 + tig];
                #pragma unroll
                for (int mf = 0; mf < 4; mf++) {
                    mma_bf16(acc[mf][nf], ah[mf], bh);
                    mma_bf16(acc[mf][nf], ah[mf], bl);
                    mma_bf16(acc[mf][nf], al[mf], bh);
                }
            }
        }
        __syncthreads();
    }

    #pragma unroll
    for (int mf = 0; mf < 4; mf++) {
        int m = bm + wm + mf * 16 + grp;
        #pragma unroll
        for (int nf = 0; nf < 4; nf++) {
            int n = bn + wn + nf * 8 + tig * 2;
            float b0 = bias ? bias[n] : 0.0f;
            float b1 = bias ? bias[n + 1] : 0.0f;
            float v0 = acc[mf][nf][0] + b0;
            float v1 = acc[mf][nf][1] + b1;
            float v2 = acc[mf][nf][2] + b0;
            float v3 = acc[mf][nf][3] + b1;
            if (RES) {
                float2 r0 = *(const float2*)&RES[(size_t)m * N + n];
                float2 r1 = *(const float2*)&RES[(size_t)(m + 8) * N + n];
                v0 += r0.x; v1 += r0.y; v2 += r1.x; v3 += r1.y;
            }
            if (relu) {
                v0 = fmaxf(v0, 0.0f); v1 = fmaxf(v1, 0.0f);
                v2 = fmaxf(v2, 0.0f); v3 = fmaxf(v3, 0.0f);
            }
            *(float2*)&C[(size_t)m * N + n]       = make_float2(v0, v1);
            *(float2*)&C[(size_t)(m + 8) * N + n] = make_float2(v2, v3);
        }
    }
}

// ---------------- tensor-core attention v2: 4 heads/CTA, 2 warps/head ---------------
// grid = BATCH*2; CTA handles heads [half*4, half*4+4). Warp w: head h'=w>>1,
// mf blocks {(w&1)*2, (w&1)*2+1}. QK^T 3-term fp16 split, softmax in regs,
// AV 2-term P split vs fp16 V.
// smem words: QH 0, QL 5120, KH 10240, KL 15360, VH 20480 (4 heads)
#define AQH 0u
#define AQL 5120u
#define AKH 10240u
#define AKL 15360u
#define AVH 20480u
#define ATTN_SMEM (25088u * 4u)   /* 100352 B */

__global__ __launch_bounds__(256, 2) void attn_mma_kernel(const float* __restrict__ qkv,
                                                          float* __restrict__ o) {
    extern __shared__ uint32_t smw[];
    int b = blockIdx.x >> 1;
    int h0 = (blockIdx.x & 1) * 4;
    int tid = threadIdx.x;
    int wid = tid >> 5, lane = tid & 31;
    int grp = lane >> 2, tig = lane & 3;

    const float scale = 0.17677669529663687f;   // 1/sqrt(32), folded into q

    // ---- cooperative load: 4 heads of q,k split fp16; v transposed fp16 ----
    #pragma unroll
    for (int it = 0; it < 8; it++) {
        int idx = it * 256 + tid;                // 0..2047
        int hh = idx >> 9;                       // 0..3
        int r = (idx >> 3) & 63;
        int j4 = idx & 7;
        size_t base = ((size_t)b * 64 + r) * 768 + (h0 + hh) * 32 + j4 * 4;
        float4 qv = *(const float4*)&qkv[base];
        float4 kv = *(const float4*)&qkv[base + 256];
        float4 vv = *(const float4*)&qkv[base + 512];
        qv.x *= scale; qv.y *= scale; qv.z *= scale; qv.w *= scale;
        uint32_t w0, l0, w1, l1;
        int qb = hh * 1280 + r * 20 + j4 * 2;
        cvt_split2_f16(qv.x, qv.y, w0, l0);
        cvt_split2_f16(qv.z, qv.w, w1, l1);
        smw[AQH + qb] = w0; smw[AQH + qb + 1] = w1;
        smw[AQL + qb] = l0; smw[AQL + qb + 1] = l1;
        cvt_split2_f16(kv.x, kv.y, w0, l0);
        cvt_split2_f16(kv.z, kv.w, w1, l1);
        smw[AKH + qb] = w0; smw[AKH + qb + 1] = w1;
        smw[AKL + qb] = l0; smw[AKL + qb + 1] = l1;
        __half* vp = (__half*)(smw + AVH) + hh * 2304;   // 1152 words/head
        vp[(j4 * 4 + 0) * 72 + r] = __float2half(vv.x);
        vp[(j4 * 4 + 1) * 72 + r] = __float2half(vv.y);
        vp[(j4 * 4 + 2) * 72 + r] = __float2half(vv.z);
        vp[(j4 * 4 + 3) * 72 + r] = __float2half(vv.w);
    }
    __syncthreads();

    // ---- per-warp: head hh, 2 mf blocks ----
    int hh = wid >> 1;
    int mfb = (wid & 1) * 2;
    const uint32_t qh0 = AQH + hh * 1280, ql0 = AQL + hh * 1280;
    const uint32_t kh0 = AKH + hh * 1280, kl0 = AKL + hh * 1280;
    const uint32_t vh0 = AVH + hh * 1152;

    float O[2][4][4];
    #pragma unroll
    for (int i = 0; i < 2; i++)
        #pragma unroll
        for (int j = 0; j < 4; j++)
            #pragma unroll
            for (int r = 0; r < 4; r++) O[i][j][r] = 0.0f;

    #pragma unroll
    for (int mi = 0; mi < 2; mi++) {
        int mf = mfb + mi;
        float S[8][4];
        #pragma unroll
        for (int nf = 0; nf < 8; nf++)
            #pragma unroll
            for (int r = 0; r < 4; r++) S[nf][r] = 0.0f;

        #pragma unroll
        for (int kc = 0; kc < 2; kc++) {
            int rA = mf * 16 + grp;
            uint32_t ah[4], al[4];
            ah[0] = smw[qh0 + rA * 20 + kc * 8 + tig];
            ah[1] = smw[qh0 + (rA + 8) * 20 + kc * 8 + tig];
            ah[2] = smw[qh0 + rA * 20 + kc * 8 + 4 + tig];
            ah[3] = smw[qh0 + (rA + 8) * 20 + kc * 8 + 4 + tig];
            al[0] = smw[ql0 + rA * 20 + kc * 8 + tig];
            al[1] = smw[ql0 + (rA + 8) * 20 + kc * 8 + tig];
            al[2] = smw[ql0 + rA * 20 + kc * 8 + 4 + tig];
            al[3] = smw[ql0 + (rA + 8) * 20 + kc * 8 + 4 + tig];
            #pragma unroll
            for (int nf = 0; nf < 8; nf++) {
                int rB = nf * 8 + grp;
                uint32_t bh[2], bl[2];
                bh[0] = smw[kh0 + rB * 20 + kc * 8 + tig];
                bh[1] = smw[kh0 + rB * 20 + kc * 8 + 4 + tig];
                bl[0] = smw[kl0 + rB * 20 + kc * 8 + tig];
                bl[1] = smw[kl0 + rB * 20 + kc * 8 + 4 + tig];
                mma_f16(S[nf], ah, bh);
                mma_f16(S[nf], ah, bl);
                mma_f16(S[nf], al, bh);
            }
        }

        float m0 = -1e30f, m1 = -1e30f;
        #pragma unroll
        for (int nf = 0; nf < 8; nf++) {
            m0 = fmaxf(m0, fmaxf(S[nf][0], S[nf][1]));
            m1 = fmaxf(m1, fmaxf(S[nf][2], S[nf][3]));
        }
        m0 = fmaxf(m0, __shfl_xor_sync(0xffffffffu, m0, 1));
        m0 = fmaxf(m0, __shfl_xor_sync(0xffffffffu, m0, 2));
        m1 = fmaxf(m1, __shfl_xor_sync(0xffffffffu, m1, 1));
        m1 = fmaxf(m1, __shfl_xor_sync(0xffffffffu, m1, 2));
        float s0 = 0.0f, s1 = 0.0f;
        #pragma unroll
        for (int nf = 0; nf < 8; nf++) {
            S[nf][0] = __expf(S[nf][0] - m0); s0 += S[nf][0];
            S[nf][1] = __expf(S[nf][1] - m0); s0 += S[nf][1];
            S[nf][2] = __expf(S[nf][2] - m1); s1 += S[nf][2];
            S[nf][3] = __expf(S[nf][3] - m1); s1 += S[nf][3];
        }
        s0 += __shfl_xor_sync(0xffffffffu, s0, 1);
        s0 += __shfl_xor_sync(0xffffffffu, s0, 2);
        s1 += __shfl_xor_sync(0xffffffffu, s1, 1);
        s1 += __shfl_xor_sync(0xffffffffu, s1, 2);
        float i0 = 1.0f / s0, i1 = 1.0f / s1;

        uint32_t PHa[8], PHb[8], PLa[8], PLb[8];
        #pragma unroll
        for (int nf = 0; nf < 8; nf++) {
            float p0 = S[nf][0] * i0, p1 = S[nf][1] * i0;
            float p2 = S[nf][2] * i1, p3 = S[nf][3] * i1;
            uint32_t ph = packh(p0, p1);
            __half2 hv = *(__half2*)&ph;
            PHa[nf] = ph;
            PLa[nf] = packh(p0 - __half2float(hv.x), p1 - __half2float(hv.y));
            ph = packh(p2, p3);
            hv = *(__half2*)&ph;
            PHb[nf] = ph;
            PLb[nf] = packh(p2 - __half2float(hv.x), p3 - __half2float(hv.y));
        }

        #pragma unroll
        for (int jc = 0; jc < 4; jc++) {
            uint32_t aph[4] = { PHa[2 * jc], PHb[2 * jc], PHa[2 * jc + 1], PHb[2 * jc + 1] };
            uint32_t apl[4] = { PLa[2 * jc], PLb[2 * jc], PLa[2 * jc + 1], PLb[2 * jc + 1] };
            #pragma unroll
            for (int no = 0; no < 4; no++) {
                int rB = no * 8 + grp;
                uint32_t bv[2];
                bv[0] = smw[vh0 + rB * 36 + jc * 8 + tig];
                bv[1] = smw[vh0 + rB * 36 + jc * 8 + 4 + tig];
                mma_f16(O[mi][no], aph, bv);
                mma_f16(O[mi][no], apl, bv);
            }
        }
    }

    // ---- epilogue ----
    #pragma unroll
    for (int mi = 0; mi < 2; mi++) {
        int row = (mfb + mi) * 16 + grp;
        #pragma unroll
        for (int no = 0; no < 4; no++) {
            int d = no * 8 + tig * 2;
            size_t ob = ((size_t)b * 64 + row) * DM + (h0 + hh) * 32 + d;
            *(float2*)&o[ob]          = make_float2(O[mi][no][0], O[mi][no][1]);
            *(float2*)&o[ob + 8 * DM] = make_float2(O[mi][no][2], O[mi][no][3]);
        }
    }
}

// ---------------- layernorm (input already contains residual): warp per row ---------
__global__ __launch_bounds__(256) void ln_kernel(float* __restrict__ x,
                                                 const float* __restrict__ src,
                                                 const float* __restrict__ gg,
                                                 const float* __restrict__ bb) {
    int wid = threadIdx.x >> 5, lane = threadIdx.x & 31;
    size_t base = ((size_t)blockIdx.x * 8 + wid) * 256;
    int c0 = lane * 4, c1 = 128 + lane * 4;
    float4 a0 = *(const float4*)&src[base + c0];
    float4 a1 = *(const float4*)&src[base + c1];
    float t[8] = { a0.x, a0.y, a0.z, a0.w, a1.x, a1.y, a1.z, a1.w };
    float s = 0.0f;
    #pragma unroll
    for (int i = 0; i < 8; i++) s += t[i];
    #pragma unroll
    for (int off = 16; off; off >>= 1) s += __shfl_xor_sync(0xffffffffu, s, off);
    float mean = s * (1.0f / 256.0f);
    float v = 0.0f;
    #pragma unroll
    for (int i = 0; i < 8; i++) { t[i] -= mean; v += t[i] * t[i]; }
    #pragma unroll
    for (int off = 16; off; off >>= 1) v += __shfl_xor_sync(0xffffffffu, v, off);
    float rstd = rsqrtf(v * (1.0f / 256.0f) + 1e-5f);
    float4 g0 = *(const float4*)&gg[c0];
    float4 g1 = *(const float4*)&gg[c1];
    float4 e0 = *(const float4*)&bb[c0];
    float4 e1 = *(const float4*)&bb[c1];
    float4 r0 = make_float4(t[0] * rstd * g0.x + e0.x, t[1] * rstd * g0.y + e0.y,
                            t[2] * rstd * g0.z + e0.z, t[3] * rstd * g0.w + e0.w);
    float4 r1 = make_float4(t[4] * rstd * g1.x + e1.x, t[5] * rstd * g1.y + e1.y,
                            t[6] * rstd * g1.z + e1.z, t[7] * rstd * g1.w + e1.w);
    *(float4*)&x[base + c0] = r0;
    *(float4*)&x[base + c1] = r1;
}

// ---------------- mean pooling ----------------
__global__ void pool_kernel(const float* __restrict__ x, float* __restrict__ pooled) {
    int b = blockIdx.x, d = threadIdx.x;
    float s = 0.0f;
    #pragma unroll 8
    for (int i = 0; i < 64; i++) s += x[((size_t)b * 64 + i) * DM + d];
    pooled[(size_t)b * DM + d] = s * (1.0f / 64.0f);
}

// ---------------- tiny head finals ----------------
__global__ void head_final_kernel(const float* __restrict__ hid,
                                  const float* __restrict__ w,
                                  const float* __restrict__ bias,
                                  float* __restrict__ out, int nout, int do_tanh) {
    int b = blockIdx.x;
    int lane = threadIdx.x;
    for (int o = 0; o < nout; o++) {
        float s = 0.0f;
        #pragma unroll
        for (int i = lane; i < 256; i += 32) s = fmaf(hid[(size_t)b * 256 + i], w[o * 256 + i], s);
        #pragma unroll
        for (int off = 16; off; off >>= 1) s += __shfl_xor_sync(0xffffffffu, s, off);
        if (lane == 0) {
            float v = s + bias[o];
            out[(size_t)b * nout + o] = do_tanh ? tanhf(v) : v;
        }
    }
}

// ---------------- host side ----------------
static inline void sgemm(const float* A, const float* W, const float* bias,
                         const float* res, float* C, int M, int N, int K, int relu) {
    dim3 g(N / 128, M / 128), blk(256);
    gemm_bf16x2<<<g, blk>>>(A, W, bias, res, C, M, N, K, relu);
}

extern "C" void kernel_launch(void* const* d_in, const int* in_sizes, int n_in,
                              void* d_out, int out_size) {
    const float* board = (const float*)d_in[0];
    const float* emb   = (const float*)d_in[1];
    const float* qkv_w = (const float*)d_in[2];
    const float* qkv_b = (const float*)d_in[3];
    const float* out_w = (const float*)d_in[4];
    const float* out_b = (const float*)d_in[5];
    const float* ln1_g = (const float*)d_in[6];
    const float* ln1_b = (const float*)d_in[7];
    const float* ln2_g = (const float*)d_in[8];
    const float* ln2_b = (const float*)d_in[9];
    const float* ff1_w = (const float*)d_in[10];
    const float* ff1_b = (const float*)d_in[11];
    const float* ff2_w = (const float*)d_in[12];
    const float* ff2_b = (const float*)d_in[13];
    const float* vw1 = (const float*)d_in[14];
    const float* vb1 = (const float*)d_in[15];
    const float* vw2 = (const float*)d_in[16];
    const float* vb2 = (const float*)d_in[17];
    const float* pw1 = (const float*)d_in[18];
    const float* pb1 = (const float*)d_in[19];
    const float* pw2 = (const float*)d_in[20];
    const float* pb2 = (const float*)d_in[21];
    const float* cw1 = (const float*)d_in[22];
    const float* cb1 = (const float*)d_in[23];
    const float* cw2 = (const float*)d_in[24];
    const float* cb2 = (const float*)d_in[25];

    float* out = (float*)d_out;
    float* out_value  = out;
    float* out_policy = out + BATCH;
    float* out_class  = out + BATCH + (size_t)BATCH * 4096;

    cudaFuncSetAttribute(attn_mma_kernel, cudaFuncAttributeMaxDynamicSharedMemorySize,
                         ATTN_SMEM);

    float *px, *pqkv, *po, *py, *pff, *ppe, *ppool, *pvh, *pch, *ph1;
    cudaGetSymbolAddress((void**)&px,    g_x);
    cudaGetSymbolAddress((void**)&pqkv,  g_qkv);
    cudaGetSymbolAddress((void**)&po,    g_o);
    cudaGetSymbolAddress((void**)&py,    g_y);
    cudaGetSymbolAddress((void**)&pff,   g_ffb);
    cudaGetSymbolAddress((void**)&ppe,   g_pe);
    cudaGetSymbolAddress((void**)&ppool, g_pooled);
    cudaGetSymbolAddress((void**)&pvh,   g_vh);
    cudaGetSymbolAddress((void**)&pch,   g_ch);
    cudaGetSymbolAddress((void**)&ph1,   g_h1);

    pe_kernel<<<SQ, DM>>>(ppe);
    embed_kernel<<<MTOK, DM>>>(board, emb, ppe, px);

    for (int l = 0; l < NL; l++) {
        const float* Wqkv = qkv_w + (size_t)l * 3 * DM * DM;
        const float* Bqkv = qkv_b + (size_t)l * 3 * DM;
        const float* Wout = out_w + (size_t)l * DM * DM;
        const float* Bout = out_b + (size_t)l * DM;
        const float* W1   = ff1_w + (size_t)l * FFD * DM;
        const float* B1   = ff1_b + (size_t)l * FFD;
        const float* W2   = ff2_w + (size_t)l * DM * FFD;
        const float* B2   = ff2_b + (size_t)l * DM;

        sgemm(px, Wqkv, Bqkv, 0, pqkv, MTOK, 3 * DM, DM, 0);
        attn_mma_kernel<<<BATCH * 2, 256, ATTN_SMEM>>>(pqkv, po);
        sgemm(po, Wout, Bout, px, py, MTOK, DM, DM, 0);        // py = x + attn_out
        ln_kernel<<<MTOK / 8, 256>>>(px, py, ln1_g + l * DM, ln1_b + l * DM);
        sgemm(px, W1, B1, 0, pff, MTOK, FFD, DM, 1);
        sgemm(pff, W2, B2, px, py, MTOK, DM, FFD, 0);          // py = x + ff_out
        ln_kernel<<<MTOK / 8, 256>>>(px, py, ln2_g + l * DM, ln2_b + l * DM);
    }

    // heads
    pool_kernel<<<BATCH, DM>>>(px, ppool);

    sgemm(ppool, vw1, vb1, 0, pvh, BATCH, 256, 256, 1);
    head_final_kernel<<<BATCH, 32>>>(pvh, vw2, vb2, out_value, 1, 1);

    sgemm(px, pw1, pb1, 0, ph1, BATCH, 1024, 16384, 1);      // x viewed as [B, 64*256]
    sgemm(ph1, pw2, pb2, 0, out_policy, BATCH, 4096, 1024, 0);

    sgemm(ppool, cw1, cb1, 0, pch, BATCH, 256, 256, 1);
    head_final_kernel<<<BATCH, 32>>>(pch, cw2, cb2, out_class, 3, 0);
}

// round 11
// speedup vs baseline: 1.6124x; 1.0316x over previous
#include <cuda_runtime.h>
#include <cuda_bf16.h>
#include <cuda_fp16.h>
#include <math.h>
#include <stdint.h>

#define BATCH 4096
#define SQ    64
#define DM    256
#define NH    8
#define FFD   1024
#define NL    6
#define MTOK  (BATCH*SQ)   /* 262144 */

// ---------------- scratch (no allocations allowed) ----------------
__device__ float  g_x[MTOK*DM];
__device__ __half g_qkv16[MTOK*3*DM];
__device__ float  g_o[MTOK*DM];
__device__ float  g_y[MTOK*DM];
__device__ float  g_ffb[MTOK*FFD];
__device__ float  g_pe[SQ*DM];
__device__ float  g_pooled[BATCH*DM];
__device__ float  g_vh[BATCH*DM];
__device__ float  g_ch[BATCH*DM];
__device__ float  g_h1[BATCH*1024];
__device__ float  g_h1a[BATCH*1024];
__device__ float  g_h1b[BATCH*1024];

// ---------------- PE precompute ----------------
__global__ void pe_kernel(float* __restrict__ pe) {
    int s = blockIdx.x, d = threadIdx.x;
    int row = s >> 3, col = s & 7;
    int m = d >> 1;
    float div = powf(10000.0f, (2.0f * (float)m) / 256.0f);
    float v = (d & 1) ? cosf((float)col / div) : sinf((float)row / div);
    pe[s * DM + d] = v;
}

// ---------------- tokens + embedding + PE ----------------
__global__ void embed_kernel(const float* __restrict__ board,
                             const float* __restrict__ emb,
                             const float* __restrict__ pe,
                             float* __restrict__ x) {
    int tokidx = blockIdx.x;
    int b = tokidx >> 6, s = tokidx & 63;
    __shared__ float ch[14];
    __shared__ int tok;
    int d = threadIdx.x;
    if (d < 14) ch[d] = board[(size_t)b * 896 + (size_t)d * 64 + s];
    __syncthreads();
    if (d == 0) {
        float mx = ch[0]; int idx = 0;
        #pragma unroll
        for (int c = 1; c < 14; c++) { if (ch[c] > mx) { mx = ch[c]; idx = c; } }
        tok = (mx > 0.0f) ? (idx + 1) : 0;
    }
    __syncthreads();
    x[(size_t)tokidx * DM + d] = emb[tok * DM + d] + pe[s * DM + d];
}

// ---------------- bf16 split helpers (GEMM — proven numerics) ----------------
__device__ __forceinline__ void cvt_split2(float x, float y, uint32_t& hi, uint32_t& lo) {
    __nv_bfloat16 hx = __float2bfloat16(x);
    __nv_bfloat16 hy = __float2bfloat16(y);
    __nv_bfloat16 lx = __float2bfloat16(x - __bfloat162float(hx));
    __nv_bfloat16 ly = __float2bfloat16(y - __bfloat162float(hy));
    hi = ((uint32_t)__bfloat16_as_ushort(hy) << 16) | (uint32_t)__bfloat16_as_ushort(hx);
    lo = ((uint32_t)__bfloat16_as_ushort(ly) << 16) | (uint32_t)__bfloat16_as_ushort(lx);
}

__device__ __forceinline__ void mma_bf16(float* c, const uint32_t* a, const uint32_t* b) {
    asm volatile(
        "mma.sync.aligned.m16n8k16.row.col.f32.bf16.bf16.f32 "
        "{%0,%1,%2,%3}, {%4,%5,%6,%7}, {%8,%9}, {%0,%1,%2,%3};\n"
        : "+f"(c[0]), "+f"(c[1]), "+f"(c[2]), "+f"(c[3])
        : "r"(a[0]), "r"(a[1]), "r"(a[2]), "r"(a[3]), "r"(b[0]), "r"(b[1]));
}

__device__ __forceinline__ void mma_f16(float* c, const uint32_t* a, const uint32_t* b) {
    asm volatile(
        "mma.sync.aligned.m16n8k16.row.col.f32.f16.f16.f32 "
        "{%0,%1,%2,%3}, {%4,%5,%6,%7}, {%8,%9}, {%0,%1,%2,%3};\n"
        : "+f"(c[0]), "+f"(c[1]), "+f"(c[2]), "+f"(c[3])
        : "r"(a[0]), "r"(a[1]), "r"(a[2]), "r"(a[3]), "r"(b[0]), "r"(b[1]));
}

__device__ __forceinline__ uint32_t packh(float a, float b) {
    __half2 t = __floats2half2_rn(a, b);
    return *(uint32_t*)&t;
}

// ---------------- bf16x3 tensor GEMM (proven mainloop; flexible epilogue) ----------
// C fp32 (+RES, +relu)  OR  C16 fp16.  kLen = k loop extent, ldk = row stride.
__global__ __launch_bounds__(256, 2) void gemm_bf16x2(
    const float* __restrict__ A, const float* __restrict__ W,
    const float* __restrict__ bias, const float* __restrict__ RES,
    float* __restrict__ C, __half* __restrict__ C16,
    int M, int N, int kLen, int ldk, int relu)
{
    __shared__ uint32_t Ah[128][20];
    __shared__ uint32_t Al[128][20];
    __shared__ uint32_t Wh[128][20];
    __shared__ uint32_t Wl[128][20];

    int tid = threadIdx.x;
    int wid = tid >> 5, lane = tid & 31;
    int grp = lane >> 2, tig = lane & 3;
    int wm = (wid >> 2) * 64;
    int wn = (wid & 3) * 32;
    int bm = blockIdx.y * 128, bn = blockIdx.x * 128;

    float acc[4][4][4];
    #pragma unroll
    for (int i = 0; i < 4; i++)
        #pragma unroll
        for (int j = 0; j < 4; j++)
            #pragma unroll
            for (int r = 0; r < 4; r++) acc[i][j][r] = 0.0f;

    const int ldr = tid >> 3;
    const int ldw = (tid & 7) << 1;

    for (int k0 = 0; k0 < kLen; k0 += 32) {
        #pragma unroll
        for (int i = 0; i < 4; i++) {
            int row = ldr + 32 * i;
            const float* ap = A + (size_t)(bm + row) * ldk + k0 + (ldw << 1);
            const float* wp = W + (size_t)(bn + row) * ldk + k0 + (ldw << 1);
            float4 av = *(const float4*)ap;
            float4 wv = *(const float4*)wp;
            uint32_t h0, l0, h1, l1;
            cvt_split2(av.x, av.y, h0, l0);
            cvt_split2(av.z, av.w, h1, l1);
            *(uint2*)&Ah[row][ldw] = make_uint2(h0, h1);
            *(uint2*)&Al[row][ldw] = make_uint2(l0, l1);
            cvt_split2(wv.x, wv.y, h0, l0);
            cvt_split2(wv.z, wv.w, h1, l1);
            *(uint2*)&Wh[row][ldw] = make_uint2(h0, h1);
            *(uint2*)&Wl[row][ldw] = make_uint2(l0, l1);
        }
        __syncthreads();

        #pragma unroll
        for (int wb = 0; wb < 16; wb += 8) {
            uint32_t ah[4][4], al[4][4];
            #pragma unroll
            for (int mf = 0; mf < 4; mf++) {
                int m = wm + mf * 16 + grp;
                ah[mf][0] = Ah[m][wb + tig];
                ah[mf][1] = Ah[m + 8][wb + tig];
                ah[mf][2] = Ah[m][wb + 4 + tig];
                ah[mf][3] = Ah[m + 8][wb + 4 + tig];
                al[mf][0] = Al[m][wb + tig];
                al[mf][1] = Al[m + 8][wb + tig];
                al[mf][2] = Al[m][wb + 4 + tig];
                al[mf][3] = Al[m + 8][wb + 4 + tig];
            }
            #pragma unroll
            for (int nf = 0; nf < 4; nf++) {
                int n = wn + nf * 8 + grp;
                uint32_t bh[2], bl[2];
                bh[0] = Wh[n][wb + tig];
                bh[1] = Wh[n][wb + 4 + tig];
                bl[0] = Wl[n][wb + tig];
                bl[1] = Wl[n][wb + 4 + tig];
                #pragma unroll
                for (int mf = 0; mf < 4; mf++) {
                    mma_bf16(acc[mf][nf], ah[mf], bh);
                    mma_bf16(acc[mf][nf], ah[mf], bl);
                    mma_bf16(acc[mf][nf], al[mf], bh);
                }
            }
        }
        __syncthreads();
    }

    #pragma unroll
    for (int mf = 0; mf < 4; mf++) {
        int m = bm + wm + mf * 16 + grp;
        #pragma unroll
        for (int nf = 0; nf < 4; nf++) {
            int n = bn + wn + nf * 8 + tig * 2;
            float b0 = bias ? bias[n] : 0.0f;
            float b1 = bias ? bias[n + 1] : 0.0f;
            float v0 = acc[mf][nf][0] + b0;
            float v1 = acc[mf][nf][1] + b1;
            float v2 = acc[mf][nf][2] + b0;
            float v3 = acc[mf][nf][3] + b1;
            if (C16) {
                __half2 h0 = __floats2half2_rn(v0, v1);
                __half2 h1 = __floats2half2_rn(v2, v3);
                *(__half2*)&C16[(size_t)m * N + n]       = h0;
                *(__half2*)&C16[(size_t)(m + 8) * N + n] = h1;
            } else {
                if (RES) {
                    float2 r0 = *(const float2*)&RES[(size_t)m * N + n];
                    float2 r1 = *(const float2*)&RES[(size_t)(m + 8) * N + n];
                    v0 += r0.x; v1 += r0.y; v2 += r1.x; v3 += r1.y;
                }
                if (relu) {
                    v0 = fmaxf(v0, 0.0f); v1 = fmaxf(v1, 0.0f);
                    v2 = fmaxf(v2, 0.0f); v3 = fmaxf(v3, 0.0f);
                }
                *(float2*)&C[(size_t)m * N + n]       = make_float2(v0, v1);
                *(float2*)&C[(size_t)(m + 8) * N + n] = make_float2(v2, v3);
            }
        }
    }
}

// ---------------- split-K combine: out = relu(a + b + bias) ----------------
__global__ void combine_relu_kernel(const float* __restrict__ a,
                                    const float* __restrict__ b,
                                    const float* __restrict__ bias,
                                    float* __restrict__ out) {
    int idx = blockIdx.x * 256 + threadIdx.x;     // over BATCH*1024/4
    int col = (idx * 4) & 1023;
    float4 va = ((const float4*)a)[idx];
    float4 vb = ((const float4*)b)[idx];
    float4 r;
    r.x = fmaxf(va.x + vb.x + bias[col],     0.0f);
    r.y = fmaxf(va.y + vb.y + bias[col + 1], 0.0f);
    r.z = fmaxf(va.z + vb.z + bias[col + 2], 0.0f);
    r.w = fmaxf(va.w + vb.w + bias[col + 3], 0.0f);
    ((float4*)out)[idx] = r;
}

// ---------------- tensor-core attention v3: fp16 qkv, single-precision mma ----------
// grid = BATCH*2; CTA = 4 heads; warp w: head w>>1, mf blocks {(w&1)*2, (w&1)*2+1}.
// Raw scores (no scale), scale folded into softmax exp (shift-invariance).
#define AQ 0u
#define AK 5120u
#define AV 10240u
#define ATTN_SMEM (14848u * 4u)   /* 59392 B */

__global__ __launch_bounds__(256, 2) void attn_mma_kernel(const __half* __restrict__ qkv,
                                                          float* __restrict__ o) {
    extern __shared__ uint32_t smw[];
    int b = blockIdx.x >> 1;
    int h0 = (blockIdx.x & 1) * 4;
    int tid = threadIdx.x;
    int wid = tid >> 5, lane = tid & 31;
    int grp = lane >> 2, tig = lane & 3;

    const float scale = 0.17677669529663687f;   // 1/sqrt(32), applied in softmax

    // ---- cooperative load: 4 heads of q,k rows; v transposed ----
    #pragma unroll
    for (int it = 0; it < 8; it++) {
        int idx = it * 256 + tid;                // 0..2047
        int hh = idx >> 9;                       // 0..3
        int r = (idx >> 3) & 63;
        int j4 = idx & 7;                        // half group: halfs j4*4..j4*4+3
        size_t base = ((size_t)b * 64 + r) * 768 + (h0 + hh) * 32 + j4 * 4;
        uint2 qw = *(const uint2*)&qkv[base];
        uint2 kw = *(const uint2*)&qkv[base + 256];
        uint2 vw = *(const uint2*)&qkv[base + 512];
        int qb = hh * 1280 + r * 20 + j4 * 2;
        smw[AQ + qb] = qw.x; smw[AQ + qb + 1] = qw.y;
        smw[AK + qb] = kw.x; smw[AK + qb + 1] = kw.y;
        __half* vp = (__half*)(smw + AV) + hh * 2304;
        __half2 v01 = *(__half2*)&vw.x;
        __half2 v23 = *(__half2*)&vw.y;
        vp[(j4 * 4 + 0) * 72 + r] = __low2half(v01);
        vp[(j4 * 4 + 1) * 72 + r] = __high2half(v01);
        vp[(j4 * 4 + 2) * 72 + r] = __low2half(v23);
        vp[(j4 * 4 + 3) * 72 + r] = __high2half(v23);
    }
    __syncthreads();

    int hh = wid >> 1;
    int mfb = (wid & 1) * 2;
    const uint32_t q0 = AQ + hh * 1280;
    const uint32_t k0 = AK + hh * 1280;
    const uint32_t v0 = AV + hh * 1152;

    float O[2][4][4];
    #pragma unroll
    for (int i = 0; i < 2; i++)
        #pragma unroll
        for (int j = 0; j < 4; j++)
            #pragma unroll
            for (int r = 0; r < 4; r++) O[i][j][r] = 0.0f;

    #pragma unroll
    for (int mi = 0; mi < 2; mi++) {
        int mf = mfb + mi;
        float S[8][4];
        #pragma unroll
        for (int nf = 0; nf < 8; nf++)
            #pragma unroll
            for (int r = 0; r < 4; r++) S[nf][r] = 0.0f;

        #pragma unroll
        for (int kc = 0; kc < 2; kc++) {
            int rA = mf * 16 + grp;
            uint32_t a[4];
            a[0] = smw[q0 + rA * 20 + kc * 8 + tig];
            a[1] = smw[q0 + (rA + 8) * 20 + kc * 8 + tig];
            a[2] = smw[q0 + rA * 20 + kc * 8 + 4 + tig];
            a[3] = smw[q0 + (rA + 8) * 20 + kc * 8 + 4 + tig];
            #pragma unroll
            for (int nf = 0; nf < 8; nf++) {
                int rB = nf * 8 + grp;
                uint32_t bb[2];
                bb[0] = smw[k0 + rB * 20 + kc * 8 + tig];
                bb[1] = smw[k0 + rB * 20 + kc * 8 + 4 + tig];
                mma_f16(S[nf], a, bb);
            }
        }

        float m0 = -1e30f, m1 = -1e30f;
        #pragma unroll
        for (int nf = 0; nf < 8; nf++) {
            m0 = fmaxf(m0, fmaxf(S[nf][0], S[nf][1]));
            m1 = fmaxf(m1, fmaxf(S[nf][2], S[nf][3]));
        }
        m0 = fmaxf(m0, __shfl_xor_sync(0xffffffffu, m0, 1));
        m0 = fmaxf(m0, __shfl_xor_sync(0xffffffffu, m0, 2));
        m1 = fmaxf(m1, __shfl_xor_sync(0xffffffffu, m1, 1));
        m1 = fmaxf(m1, __shfl_xor_sync(0xffffffffu, m1, 2));
        float s0 = 0.0f, s1 = 0.0f;
        #pragma unroll
        for (int nf = 0; nf < 8; nf++) {
            S[nf][0] = __expf((S[nf][0] - m0) * scale); s0 += S[nf][0];
            S[nf][1] = __expf((S[nf][1] - m0) * scale); s0 += S[nf][1];
            S[nf][2] = __expf((S[nf][2] - m1) * scale); s1 += S[nf][2];
            S[nf][3] = __expf((S[nf][3] - m1) * scale); s1 += S[nf][3];
        }
        s0 += __shfl_xor_sync(0xffffffffu, s0, 1);
        s0 += __shfl_xor_sync(0xffffffffu, s0, 2);
        s1 += __shfl_xor_sync(0xffffffffu, s1, 1);
        s1 += __shfl_xor_sync(0xffffffffu, s1, 2);
        float i0 = 1.0f / s0, i1 = 1.0f / s1;

        uint32_t PHa[8], PHb[8];
        #pragma unroll
        for (int nf = 0; nf < 8; nf++) {
            PHa[nf] = packh(S[nf][0] * i0, S[nf][1] * i0);
            PHb[nf] = packh(S[nf][2] * i1, S[nf][3] * i1);
        }

        #pragma unroll
        for (int jc = 0; jc < 4; jc++) {
            uint32_t a2[4] = { PHa[2 * jc], PHb[2 * jc], PHa[2 * jc + 1], PHb[2 * jc + 1] };
            #pragma unroll
            for (int no = 0; no < 4; no++) {
                int rB = no * 8 + grp;
                uint32_t bv[2];
                bv[0] = smw[v0 + rB * 36 + jc * 8 + tig];
                bv[1] = smw[v0 + rB * 36 + jc * 8 + 4 + tig];
                mma_f16(O[mi][no], a2, bv);
            }
        }
    }

    #pragma unroll
    for (int mi = 0; mi < 2; mi++) {
        int row = (mfb + mi) * 16 + grp;
        #pragma unroll
        for (int no = 0; no < 4; no++) {
            int d = no * 8 + tig * 2;
            size_t ob = ((size_t)b * 64 + row) * DM + (h0 + hh) * 32 + d;
            *(float2*)&o[ob]          = make_float2(O[mi][no][0], O[mi][no][1]);
            *(float2*)&o[ob + 8 * DM] = make_float2(O[mi][no][2], O[mi][no][3]);
        }
    }
}

// ---------------- layernorm (input already contains residual): warp per row ---------
__global__ __launch_bounds__(256) void ln_kernel(float* __restrict__ x,
                                                 const float* __restrict__ src,
                                                 const float* __restrict__ gg,
                                                 const float* __restrict__ bb) {
    int wid = threadIdx.x >> 5, lane = threadIdx.x & 31;
    size_t base = ((size_t)blockIdx.x * 8 + wid) * 256;
    int c0 = lane * 4, c1 = 128 + lane * 4;
    float4 a0 = *(const float4*)&src[base + c0];
    float4 a1 = *(const float4*)&src[base + c1];
    float t[8] = { a0.x, a0.y, a0.z, a0.w, a1.x, a1.y, a1.z, a1.w };
    float s = 0.0f;
    #pragma unroll
    for (int i = 0; i < 8; i++) s += t[i];
    #pragma unroll
    for (int off = 16; off; off >>= 1) s += __shfl_xor_sync(0xffffffffu, s, off);
    float mean = s * (1.0f / 256.0f);
    float v = 0.0f;
    #pragma unroll
    for (int i = 0; i < 8; i++) { t[i] -= mean; v += t[i] * t[i]; }
    #pragma unroll
    for (int off = 16; off; off >>= 1) v += __shfl_xor_sync(0xffffffffu, v, off);
    float rstd = rsqrtf(v * (1.0f / 256.0f) + 1e-5f);
    float4 g0 = *(const float4*)&gg[c0];
    float4 g1 = *(const float4*)&gg[c1];
    float4 e0 = *(const float4*)&bb[c0];
    float4 e1 = *(const float4*)&bb[c1];
    float4 r0 = make_float4(t[0] * rstd * g0.x + e0.x, t[1] * rstd * g0.y + e0.y,
                            t[2] * rstd * g0.z + e0.z, t[3] * rstd * g0.w + e0.w);
    float4 r1 = make_float4(t[4] * rstd * g1.x + e1.x, t[5] * rstd * g1.y + e1.y,
                            t[6] * rstd * g1.z + e1.z, t[7] * rstd * g1.w + e1.w);
    *(float4*)&x[base + c0] = r0;
    *(float4*)&x[base + c1] = r1;
}

// ---------------- mean pooling ----------------
__global__ void pool_kernel(const float* __restrict__ x, float* __restrict__ pooled) {
    int b = blockIdx.x, d = threadIdx.x;
    float s = 0.0f;
    #pragma unroll 8
    for (int i = 0; i < 64; i++) s += x[((size_t)b * 64 + i) * DM + d];
    pooled[(size_t)b * DM + d] = s * (1.0f / 64.0f);
}

// ---------------- tiny head finals ----------------
__global__ void head_final_kernel(const float* __restrict__ hid,
                                  const float* __restrict__ w,
                                  const float* __restrict__ bias,
                                  float* __restrict__ out, int nout, int do_tanh) {
    int b = blockIdx.x;
    int lane = threadIdx.x;
    for (int o = 0; o < nout; o++) {
        float s = 0.0f;
        #pragma unroll
        for (int i = lane; i < 256; i += 32) s = fmaf(hid[(size_t)b * 256 + i], w[o * 256 + i], s);
        #pragma unroll
        for (int off = 16; off; off >>= 1) s += __shfl_xor_sync(0xffffffffu, s, off);
        if (lane == 0) {
            float v = s + bias[o];
            out[(size_t)b * nout + o] = do_tanh ? tanhf(v) : v;
        }
    }
}

// ---------------- host side ----------------
static inline void sgemm(const float* A, const float* W, const float* bias,
                         const float* res, float* C, __half* C16,
                         int M, int N, int kLen, int ldk, int relu) {
    dim3 g(N / 128, M / 128), blk(256);
    gemm_bf16x2<<<g, blk>>>(A, W, bias, res, C, C16, M, N, kLen, ldk, relu);
}

extern "C" void kernel_launch(void* const* d_in, const int* in_sizes, int n_in,
                              void* d_out, int out_size) {
    const float* board = (const float*)d_in[0];
    const float* emb   = (const float*)d_in[1];
    const float* qkv_w = (const float*)d_in[2];
    const float* qkv_b = (const float*)d_in[3];
    const float* out_w = (const float*)d_in[4];
    const float* out_b = (const float*)d_in[5];
    const float* ln1_g = (const float*)d_in[6];
    const float* ln1_b = (const float*)d_in[7];
    const float* ln2_g = (const float*)d_in[8];
    const float* ln2_b = (const float*)d_in[9];
    const float* ff1_w = (const float*)d_in[10];
    const float* ff1_b = (const float*)d_in[11];
    const float* ff2_w = (const float*)d_in[12];
    const float* ff2_b = (const float*)d_in[13];
    const float* vw1 = (const float*)d_in[14];
    const float* vb1 = (const float*)d_in[15];
    const float* vw2 = (const float*)d_in[16];
    const float* vb2 = (const float*)d_in[17];
    const float* pw1 = (const float*)d_in[18];
    const float* pb1 = (const float*)d_in[19];
    const float* pw2 = (const float*)d_in[20];
    const float* pb2 = (const float*)d_in[21];
    const float* cw1 = (const float*)d_in[22];
    const float* cb1 = (const float*)d_in[23];
    const float* cw2 = (const float*)d_in[24];
    const float* cb2 = (const float*)d_in[25];

    float* out = (float*)d_out;
    float* out_value  = out;
    float* out_policy = out + BATCH;
    float* out_class  = out + BATCH + (size_t)BATCH * 4096;

    cudaFuncSetAttribute(attn_mma_kernel, cudaFuncAttributeMaxDynamicSharedMemorySize,
                         ATTN_SMEM);

    float *px, *po, *py, *pff, *ppe, *ppool, *pvh, *pch, *ph1, *ph1a, *ph1b;
    __half* pqkv;
    cudaGetSymbolAddress((void**)&px,    g_x);
    cudaGetSymbolAddress((void**)&pqkv,  g_qkv16);
    cudaGetSymbolAddress((void**)&po,    g_o);
    cudaGetSymbolAddress((void**)&py,    g_y);
    cudaGetSymbolAddress((void**)&pff,   g_ffb);
    cudaGetSymbolAddress((void**)&ppe,   g_pe);
    cudaGetSymbolAddress((void**)&ppool, g_pooled);
    cudaGetSymbolAddress((void**)&pvh,   g_vh);
    cudaGetSymbolAddress((void**)&pch,   g_ch);
    cudaGetSymbolAddress((void**)&ph1,   g_h1);
    cudaGetSymbolAddress((void**)&ph1a,  g_h1a);
    cudaGetSymbolAddress((void**)&ph1b,  g_h1b);

    pe_kernel<<<SQ, DM>>>(ppe);
    embed_kernel<<<MTOK, DM>>>(board, emb, ppe, px);

    for (int l = 0; l < NL; l++) {
        const float* Wqkv = qkv_w + (size_t)l * 3 * DM * DM;
        const float* Bqkv = qkv_b + (size_t)l * 3 * DM;
        const float* Wout = out_w + (size_t)l * DM * DM;
        const float* Bout = out_b + (size_t)l * DM;
        const float* W1   = ff1_w + (size_t)l * FFD * DM;
        const float* B1   = ff1_b + (size_t)l * FFD;
        const float* W2   = ff2_w + (size_t)l * DM * FFD;
        const float* B2   = ff2_b + (size_t)l * DM;

        sgemm(px, Wqkv, Bqkv, 0, 0, pqkv, MTOK, 768, 256, 256, 0);     // qkv fp16
        attn_mma_kernel<<<BATCH * 2, 256, ATTN_SMEM>>>(pqkv, po);
        sgemm(po, Wout, Bout, px, py, 0, MTOK, 256, 256, 256, 0);      // py = x + attn
        ln_kernel<<<MTOK / 8, 256>>>(px, py, ln1_g + l * DM, ln1_b + l * DM);
        sgemm(px, W1, B1, 0, pff, 0, MTOK, 1024, 256, 256, 1);
        sgemm(pff, W2, B2, px, py, 0, MTOK, 256, 1024, 1024, 0);       // py = x + ff
        ln_kernel<<<MTOK / 8, 256>>>(px, py, ln2_g + l * DM, ln2_b + l * DM);
    }

    // heads
    pool_kernel<<<BATCH, DM>>>(px, ppool);

    sgemm(ppool, vw1, vb1, 0, pvh, 0, BATCH, 256, 256, 256, 1);
    head_final_kernel<<<BATCH, 32>>>(pvh, vw2, vb2, out_value, 1, 1);

    // policy: split-K=2 over K=16384 (x viewed as [B, 64*256])
    sgemm(px,        pw1,        0, 0, ph1a, 0, BATCH, 1024, 8192, 16384, 0);
    sgemm(px + 8192, pw1 + 8192, 0, 0, ph1b, 0, BATCH, 1024, 8192, 16384, 0);
    combine_relu_kernel<<<BATCH * 1024 / 4 / 256, 256>>>(ph1a, ph1b, pb1, ph1);
    sgemm(ph1, pw2, pb2, 0, out_policy, 0, BATCH, 4096, 1024, 1024, 0);

    sgemm(ppool, cw1, cb1, 0, pch, 0, BATCH, 256, 256, 256, 1);
    head_final_kernel<<<BATCH, 32>>>(pch, cw2, cb2, out_class, 3, 0);
}

// round 12
// speedup vs baseline: 2.0790x; 1.2894x over previous
#include <cuda_runtime.h>
#include <cuda_bf16.h>
#include <cuda_fp16.h>
#include <math.h>
#include <stdint.h>

#define BATCH 4096
#define SQ    64
#define DM    256
#define NH    8
#define FFD   1024
#define NL    6
#define MTOK  (BATCH*SQ)   /* 262144 */

// ---------------- scratch (no allocations allowed) ----------------
__device__ float  g_x[MTOK*DM];
__device__ __half g_qkv16[MTOK*3*DM];
__device__ float  g_o[MTOK*DM];
__device__ float  g_y[MTOK*DM];
__device__ float  g_ffb[MTOK*FFD];
__device__ float  g_pe[SQ*DM];
__device__ float  g_pooled[BATCH*DM];
__device__ float  g_vh[BATCH*DM];
__device__ float  g_ch[BATCH*DM];
__device__ float  g_h1[BATCH*1024];
__device__ float  g_h1a[BATCH*1024];
__device__ float  g_h1b[BATCH*1024];

// ---------------- PE precompute ----------------
__global__ void pe_kernel(float* __restrict__ pe) {
    int s = blockIdx.x, d = threadIdx.x;
    int row = s >> 3, col = s & 7;
    int m = d >> 1;
    float div = powf(10000.0f, (2.0f * (float)m) / 256.0f);
    float v = (d & 1) ? cosf((float)col / div) : sinf((float)row / div);
    pe[s * DM + d] = v;
}

// ---------------- tokens + embedding + PE ----------------
__global__ void embed_kernel(const float* __restrict__ board,
                             const float* __restrict__ emb,
                             const float* __restrict__ pe,
                             float* __restrict__ x) {
    int tokidx = blockIdx.x;
    int b = tokidx >> 6, s = tokidx & 63;
    __shared__ float ch[14];
    __shared__ int tok;
    int d = threadIdx.x;
    if (d < 14) ch[d] = board[(size_t)b * 896 + (size_t)d * 64 + s];
    __syncthreads();
    if (d == 0) {
        float mx = ch[0]; int idx = 0;
        #pragma unroll
        for (int c = 1; c < 14; c++) { if (ch[c] > mx) { mx = ch[c]; idx = c; } }
        tok = (mx > 0.0f) ? (idx + 1) : 0;
    }
    __syncthreads();
    x[(size_t)tokidx * DM + d] = emb[tok * DM + d] + pe[s * DM + d];
}

// ---------------- fp16 helpers ----------------
__device__ __forceinline__ uint32_t packh(float a, float b) {
    __half2 t = __floats2half2_rn(a, b);
    return *(uint32_t*)&t;
}

// x = hi + lo (lo unscaled; for O(1) activations lo ~2^-12|x| is fp16-normal)
__device__ __forceinline__ void cvt_split2u(float x, float y, uint32_t& hi, uint32_t& lo) {
    __half hx = __float2half(x);
    __half hy = __float2half(y);
    hi = ((uint32_t)__half_as_ushort(hy) << 16) | (uint32_t)__half_as_ushort(hx);
    lo = packh(x - __half2float(hx), y - __half2float(hy));
}

__device__ __forceinline__ void mma_f16(float* c, const uint32_t* a, const uint32_t* b) {
    asm volatile(
        "mma.sync.aligned.m16n8k16.row.col.f32.f16.f16.f32 "
        "{%0,%1,%2,%3}, {%4,%5,%6,%7}, {%8,%9}, {%0,%1,%2,%3};\n"
        : "+f"(c[0]), "+f"(c[1]), "+f"(c[2]), "+f"(c[3])
        : "r"(a[0]), "r"(a[1]), "r"(a[2]), "r"(a[3]), "r"(b[0]), "r"(b[1]));
}

// ---------------- fp16 2-term tensor GEMM ----------------
// C[M,N] = A[M,K] @ W[N,K]^T + bias;  D = (Ah + Al) * f16(W), single fp32 accum.
// C fp32 (+RES, +relu)  OR  C16 fp16.  kLen = k loop extent, ldk = row stride.
__global__ __launch_bounds__(256, 2) void gemm_f16x2(
    const float* __restrict__ A, const float* __restrict__ W,
    const float* __restrict__ bias, const float* __restrict__ RES,
    float* __restrict__ C, __half* __restrict__ C16,
    int M, int N, int kLen, int ldk, int relu)
{
    __shared__ uint32_t Ah[128][20];
    __shared__ uint32_t Al[128][20];
    __shared__ uint32_t Ws[128][20];

    int tid = threadIdx.x;
    int wid = tid >> 5, lane = tid & 31;
    int grp = lane >> 2, tig = lane & 3;
    int wm = (wid >> 2) * 64;
    int wn = (wid & 3) * 32;
    int bm = blockIdx.y * 128, bn = blockIdx.x * 128;

    float acc[4][4][4];
    #pragma unroll
    for (int i = 0; i < 4; i++)
        #pragma unroll
        for (int j = 0; j < 4; j++)
            #pragma unroll
            for (int r = 0; r < 4; r++) acc[i][j][r] = 0.0f;

    const int ldr = tid >> 3;
    const int ldw = (tid & 7) << 1;

    for (int k0 = 0; k0 < kLen; k0 += 32) {
        #pragma unroll
        for (int i = 0; i < 4; i++) {
            int row = ldr + 32 * i;
            const float* ap = A + (size_t)(bm + row) * ldk + k0 + (ldw << 1);
            const float* wp = W + (size_t)(bn + row) * ldk + k0 + (ldw << 1);
            float4 av = *(const float4*)ap;
            float4 wv = *(const float4*)wp;
            uint32_t h0, l0, h1, l1;
            cvt_split2u(av.x, av.y, h0, l0);
            cvt_split2u(av.z, av.w, h1, l1);
            *(uint2*)&Ah[row][ldw] = make_uint2(h0, h1);
            *(uint2*)&Al[row][ldw] = make_uint2(l0, l1);
            *(uint2*)&Ws[row][ldw] = make_uint2(packh(wv.x, wv.y), packh(wv.z, wv.w));
        }
        __syncthreads();

        #pragma unroll
        for (int wb = 0; wb < 16; wb += 8) {
            uint32_t ah[4][4], al[4][4];
            #pragma unroll
            for (int mf = 0; mf < 4; mf++) {
                int m = wm + mf * 16 + grp;
                ah[mf][0] = Ah[m][wb + tig];
                ah[mf][1] = Ah[m + 8][wb + tig];
                ah[mf][2] = Ah[m][wb + 4 + tig];
                ah[mf][3] = Ah[m + 8][wb + 4 + tig];
                al[mf][0] = Al[m][wb + tig];
                al[mf][1] = Al[m + 8][wb + tig];
                al[mf][2] = Al[m][wb + 4 + tig];
                al[mf][3] = Al[m + 8][wb + 4 + tig];
            }
            #pragma unroll
            for (int nf = 0; nf < 4; nf++) {
                int n = wn + nf * 8 + grp;
                uint32_t bh[2];
                bh[0] = Ws[n][wb + tig];
                bh[1] = Ws[n][wb + 4 + tig];
                #pragma unroll
                for (int mf = 0; mf < 4; mf++) {
                    mma_f16(acc[mf][nf], ah[mf], bh);
                    mma_f16(acc[mf][nf], al[mf], bh);
                }
            }
        }
        __syncthreads();
    }

    #pragma unroll
    for (int mf = 0; mf < 4; mf++) {
        int m = bm + wm + mf * 16 + grp;
        #pragma unroll
        for (int nf = 0; nf < 4; nf++) {
            int n = bn + wn + nf * 8 + tig * 2;
            float b0 = bias ? bias[n] : 0.0f;
            float b1 = bias ? bias[n + 1] : 0.0f;
            float v0 = acc[mf][nf][0] + b0;
            float v1 = acc[mf][nf][1] + b1;
            float v2 = acc[mf][nf][2] + b0;
            float v3 = acc[mf][nf][3] + b1;
            if (C16) {
                __half2 h0 = __floats2half2_rn(v0, v1);
                __half2 h1 = __floats2half2_rn(v2, v3);
                *(__half2*)&C16[(size_t)m * N + n]       = h0;
                *(__half2*)&C16[(size_t)(m + 8) * N + n] = h1;
            } else {
                if (RES) {
                    float2 r0 = *(const float2*)&RES[(size_t)m * N + n];
                    float2 r1 = *(const float2*)&RES[(size_t)(m + 8) * N + n];
                    v0 += r0.x; v1 += r0.y; v2 += r1.x; v3 += r1.y;
                }
                if (relu) {
                    v0 = fmaxf(v0, 0.0f); v1 = fmaxf(v1, 0.0f);
                    v2 = fmaxf(v2, 0.0f); v3 = fmaxf(v3, 0.0f);
                }
                *(float2*)&C[(size_t)m * N + n]       = make_float2(v0, v1);
                *(float2*)&C[(size_t)(m + 8) * N + n] = make_float2(v2, v3);
            }
        }
    }
}

// ---------------- split-K combine: out = relu(a + b + bias) ----------------
__global__ void combine_relu_kernel(const float* __restrict__ a,
                                    const float* __restrict__ b,
                                    const float* __restrict__ bias,
                                    float* __restrict__ out) {
    int idx = blockIdx.x * 256 + threadIdx.x;
    int col = (idx * 4) & 1023;
    float4 va = ((const float4*)a)[idx];
    float4 vb = ((const float4*)b)[idx];
    float4 r;
    r.x = fmaxf(va.x + vb.x + bias[col],     0.0f);
    r.y = fmaxf(va.y + vb.y + bias[col + 1], 0.0f);
    r.z = fmaxf(va.z + vb.z + bias[col + 2], 0.0f);
    r.w = fmaxf(va.w + vb.w + bias[col + 3], 0.0f);
    ((float4*)out)[idx] = r;
}

// ---------------- tensor-core attention v3 (proven round 11) ----------------
#define AQ 0u
#define AK 5120u
#define AV 10240u
#define ATTN_SMEM (14848u * 4u)   /* 59392 B */

__global__ __launch_bounds__(256, 2) void attn_mma_kernel(const __half* __restrict__ qkv,
                                                          float* __restrict__ o) {
    extern __shared__ uint32_t smw[];
    int b = blockIdx.x >> 1;
    int h0 = (blockIdx.x & 1) * 4;
    int tid = threadIdx.x;
    int wid = tid >> 5, lane = tid & 31;
    int grp = lane >> 2, tig = lane & 3;

    const float scale = 0.17677669529663687f;

    #pragma unroll
    for (int it = 0; it < 8; it++) {
        int idx = it * 256 + tid;
        int hh = idx >> 9;
        int r = (idx >> 3) & 63;
        int j4 = idx & 7;
        size_t base = ((size_t)b * 64 + r) * 768 + (h0 + hh) * 32 + j4 * 4;
        uint2 qw = *(const uint2*)&qkv[base];
        uint2 kw = *(const uint2*)&qkv[base + 256];
        uint2 vw = *(const uint2*)&qkv[base + 512];
        int qb = hh * 1280 + r * 20 + j4 * 2;
        smw[AQ + qb] = qw.x; smw[AQ + qb + 1] = qw.y;
        smw[AK + qb] = kw.x; smw[AK + qb + 1] = kw.y;
        __half* vp = (__half*)(smw + AV) + hh * 2304;
        __half2 v01 = *(__half2*)&vw.x;
        __half2 v23 = *(__half2*)&vw.y;
        vp[(j4 * 4 + 0) * 72 + r] = __low2half(v01);
        vp[(j4 * 4 + 1) * 72 + r] = __high2half(v01);
        vp[(j4 * 4 + 2) * 72 + r] = __low2half(v23);
        vp[(j4 * 4 + 3) * 72 + r] = __high2half(v23);
    }
    __syncthreads();

    int hh = wid >> 1;
    int mfb = (wid & 1) * 2;
    const uint32_t q0 = AQ + hh * 1280;
    const uint32_t k0 = AK + hh * 1280;
    const uint32_t v0 = AV + hh * 1152;

    float O[2][4][4];
    #pragma unroll
    for (int i = 0; i < 2; i++)
        #pragma unroll
        for (int j = 0; j < 4; j++)
            #pragma unroll
            for (int r = 0; r < 4; r++) O[i][j][r] = 0.0f;

    #pragma unroll
    for (int mi = 0; mi < 2; mi++) {
        int mf = mfb + mi;
        float S[8][4];
        #pragma unroll
        for (int nf = 0; nf < 8; nf++)
            #pragma unroll
            for (int r = 0; r < 4; r++) S[nf][r] = 0.0f;

        #pragma unroll
        for (int kc = 0; kc < 2; kc++) {
            int rA = mf * 16 + grp;
            uint32_t a[4];
            a[0] = smw[q0 + rA * 20 + kc * 8 + tig];
            a[1] = smw[q0 + (rA + 8) * 20 + kc * 8 + tig];
            a[2] = smw[q0 + rA * 20 + kc * 8 + 4 + tig];
            a[3] = smw[q0 + (rA + 8) * 20 + kc * 8 + 4 + tig];
            #pragma unroll
            for (int nf = 0; nf < 8; nf++) {
                int rB = nf * 8 + grp;
                uint32_t bb[2];
                bb[0] = smw[k0 + rB * 20 + kc * 8 + tig];
                bb[1] = smw[k0 + rB * 20 + kc * 8 + 4 + tig];
                mma_f16(S[nf], a, bb);
            }
        }

        float m0 = -1e30f, m1 = -1e30f;
        #pragma unroll
        for (int nf = 0; nf < 8; nf++) {
            m0 = fmaxf(m0, fmaxf(S[nf][0], S[nf][1]));
            m1 = fmaxf(m1, fmaxf(S[nf][2], S[nf][3]));
        }
        m0 = fmaxf(m0, __shfl_xor_sync(0xffffffffu, m0, 1));
        m0 = fmaxf(m0, __shfl_xor_sync(0xffffffffu, m0, 2));
        m1 = fmaxf(m1, __shfl_xor_sync(0xffffffffu, m1, 1));
        m1 = fmaxf(m1, __shfl_xor_sync(0xffffffffu, m1, 2));
        float s0 = 0.0f, s1 = 0.0f;
        #pragma unroll
        for (int nf = 0; nf < 8; nf++) {
            S[nf][0] = __expf((S[nf][0] - m0) * scale); s0 += S[nf][0];
            S[nf][1] = __expf((S[nf][1] - m0) * scale); s0 += S[nf][1];
            S[nf][2] = __expf((S[nf][2] - m1) * scale); s1 += S[nf][2];
            S[nf][3] = __expf((S[nf][3] - m1) * scale); s1 += S[nf][3];
        }
        s0 += __shfl_xor_sync(0xffffffffu, s0, 1);
        s0 += __shfl_xor_sync(0xffffffffu, s0, 2);
        s1 += __shfl_xor_sync(0xffffffffu, s1, 1);
        s1 += __shfl_xor_sync(0xffffffffu, s1, 2);
        float i0 = 1.0f / s0, i1 = 1.0f / s1;

        uint32_t PHa[8], PHb[8];
        #pragma unroll
        for (int nf = 0; nf < 8; nf++) {
            PHa[nf] = packh(S[nf][0] * i0, S[nf][1] * i0);
            PHb[nf] = packh(S[nf][2] * i1, S[nf][3] * i1);
        }

        #pragma unroll
        for (int jc = 0; jc < 4; jc++) {
            uint32_t a2[4] = { PHa[2 * jc], PHb[2 * jc], PHa[2 * jc + 1], PHb[2 * jc + 1] };
            #pragma unroll
            for (int no = 0; no < 4; no++) {
                int rB = no * 8 + grp;
                uint32_t bv[2];
                bv[0] = smw[v0 + rB * 36 + jc * 8 + tig];
                bv[1] = smw[v0 + rB * 36 + jc * 8 + 4 + tig];
                mma_f16(O[mi][no], a2, bv);
            }
        }
    }

    #pragma unroll
    for (int mi = 0; mi < 2; mi++) {
        int row = (mfb + mi) * 16 + grp;
        #pragma unroll
        for (int no = 0; no < 4; no++) {
            int d = no * 8 + tig * 2;
            size_t ob = ((size_t)b * 64 + row) * DM + (h0 + hh) * 32 + d;
            *(float2*)&o[ob]          = make_float2(O[mi][no][0], O[mi][no][1]);
            *(float2*)&o[ob + 8 * DM] = make_float2(O[mi][no][2], O[mi][no][3]);
        }
    }
}

// ---------------- layernorm (input already contains residual): warp per row ---------
__global__ __launch_bounds__(256) void ln_kernel(float* __restrict__ x,
                                                 const float* __restrict__ src,
                                                 const float* __restrict__ gg,
                                                 const float* __restrict__ bb) {
    int wid = threadIdx.x >> 5, lane = threadIdx.x & 31;
    size_t base = ((size_t)blockIdx.x * 8 + wid) * 256;
    int c0 = lane * 4, c1 = 128 + lane * 4;
    float4 a0 = *(const float4*)&src[base + c0];
    float4 a1 = *(const float4*)&src[base + c1];
    float t[8] = { a0.x, a0.y, a0.z, a0.w, a1.x, a1.y, a1.z, a1.w };
    float s = 0.0f;
    #pragma unroll
    for (int i = 0; i < 8; i++) s += t[i];
    #pragma unroll
    for (int off = 16; off; off >>= 1) s += __shfl_xor_sync(0xffffffffu, s, off);
    float mean = s * (1.0f / 256.0f);
    float v = 0.0f;
    #pragma unroll
    for (int i = 0; i < 8; i++) { t[i] -= mean; v += t[i] * t[i]; }
    #pragma unroll
    for (int off = 16; off; off >>= 1) v += __shfl_xor_sync(0xffffffffu, v, off);
    float rstd = rsqrtf(v * (1.0f / 256.0f) + 1e-5f);
    float4 g0 = *(const float4*)&gg[c0];
    float4 g1 = *(const float4*)&gg[c1];
    float4 e0 = *(const float4*)&bb[c0];
    float4 e1 = *(const float4*)&bb[c1];
    float4 r0 = make_float4(t[0] * rstd * g0.x + e0.x, t[1] * rstd * g0.y + e0.y,
                            t[2] * rstd * g0.z + e0.z, t[3] * rstd * g0.w + e0.w);
    float4 r1 = make_float4(t[4] * rstd * g1.x + e1.x, t[5] * rstd * g1.y + e1.y,
                            t[6] * rstd * g1.z + e1.z, t[7] * rstd * g1.w + e1.w);
    *(float4*)&x[base + c0] = r0;
    *(float4*)&x[base + c1] = r1;
}

// ---------------- mean pooling ----------------
__global__ void pool_kernel(const float* __restrict__ x, float* __restrict__ pooled) {
    int b = blockIdx.x, d = threadIdx.x;
    float s = 0.0f;
    #pragma unroll 8
    for (int i = 0; i < 64; i++) s += x[((size_t)b * 64 + i) * DM + d];
    pooled[(size_t)b * DM + d] = s * (1.0f / 64.0f);
}

// ---------------- tiny head finals ----------------
__global__ void head_final_kernel(const float* __restrict__ hid,
                                  const float* __restrict__ w,
                                  const float* __restrict__ bias,
                                  float* __restrict__ out, int nout, int do_tanh) {
    int b = blockIdx.x;
    int lane = threadIdx.x;
    for (int o = 0; o < nout; o++) {
        float s = 0.0f;
        #pragma unroll
        for (int i = lane; i < 256; i += 32) s = fmaf(hid[(size_t)b * 256 + i], w[o * 256 + i], s);
        #pragma unroll
        for (int off = 16; off; off >>= 1) s += __shfl_xor_sync(0xffffffffu, s, off);
        if (lane == 0) {
            float v = s + bias[o];
            out[(size_t)b * nout + o] = do_tanh ? tanhf(v) : v;
        }
    }
}

// ---------------- host side ----------------
static inline void sgemm(const float* A, const float* W, const float* bias,
                         const float* res, float* C, __half* C16,
                         int M, int N, int kLen, int ldk, int relu) {
    dim3 g(N / 128, M / 128), blk(256);
    gemm_f16x2<<<g, blk>>>(A, W, bias, res, C, C16, M, N, kLen, ldk, relu);
}

extern "C" void kernel_launch(void* const* d_in, const int* in_sizes, int n_in,
                              void* d_out, int out_size) {
    const float* board = (const float*)d_in[0];
    const float* emb   = (const float*)d_in[1];
    const float* qkv_w = (const float*)d_in[2];
    const float* qkv_b = (const float*)d_in[3];
    const float* out_w = (const float*)d_in[4];
    const float* out_b = (const float*)d_in[5];
    const float* ln1_g = (const float*)d_in[6];
    const float* ln1_b = (const float*)d_in[7];
    const float* ln2_g = (const float*)d_in[8];
    const float* ln2_b = (const float*)d_in[9];
    const float* ff1_w = (const float*)d_in[10];
    const float* ff1_b = (const float*)d_in[11];
    const float* ff2_w = (const float*)d_in[12];
    const float* ff2_b = (const float*)d_in[13];
    const float* vw1 = (const float*)d_in[14];
    const float* vb1 = (const float*)d_in[15];
    const float* vw2 = (const float*)d_in[16];
    const float* vb2 = (const float*)d_in[17];
    const float* pw1 = (const float*)d_in[18];
    const float* pb1 = (const float*)d_in[19];
    const float* pw2 = (const float*)d_in[20];
    const float* pb2 = (const float*)d_in[21];
    const float* cw1 = (const float*)d_in[22];
    const float* cb1 = (const float*)d_in[23];
    const float* cw2 = (const float*)d_in[24];
    const float* cb2 = (const float*)d_in[25];

    float* out = (float*)d_out;
    float* out_value  = out;
    float* out_policy = out + BATCH;
    float* out_class  = out + BATCH + (size_t)BATCH * 4096;

    cudaFuncSetAttribute(attn_mma_kernel, cudaFuncAttributeMaxDynamicSharedMemorySize,
                         ATTN_SMEM);

    float *px, *po, *py, *pff, *ppe, *ppool, *pvh, *pch, *ph1, *ph1a, *ph1b;
    __half* pqkv;
    cudaGetSymbolAddress((void**)&px,    g_x);
    cudaGetSymbolAddress((void**)&pqkv,  g_qkv16);
    cudaGetSymbolAddress((void**)&po,    g_o);
    cudaGetSymbolAddress((void**)&py,    g_y);
    cudaGetSymbolAddress((void**)&pff,   g_ffb);
    cudaGetSymbolAddress((void**)&ppe,   g_pe);
    cudaGetSymbolAddress((void**)&ppool, g_pooled);
    cudaGetSymbolAddress((void**)&pvh,   g_vh);
    cudaGetSymbolAddress((void**)&pch,   g_ch);
    cudaGetSymbolAddress((void**)&ph1,   g_h1);
    cudaGetSymbolAddress((void**)&ph1a,  g_h1a);
    cudaGetSymbolAddress((void**)&ph1b,  g_h1b);

    pe_kernel<<<SQ, DM>>>(ppe);
    embed_kernel<<<MTOK, DM>>>(board, emb, ppe, px);

    for (int l = 0; l < NL; l++) {
        const float* Wqkv = qkv_w + (size_t)l * 3 * DM * DM;
        const float* Bqkv = qkv_b + (size_t)l * 3 * DM;
        const float* Wout = out_w + (size_t)l * DM * DM;
        const float* Bout = out_b + (size_t)l * DM;
        const float* W1   = ff1_w + (size_t)l * FFD * DM;
        const float* B1   = ff1_b + (size_t)l * FFD;
        const float* W2   = ff2_w + (size_t)l * DM * FFD;
        const float* B2   = ff2_b + (size_t)l * DM;

        sgemm(px, Wqkv, Bqkv, 0, 0, pqkv, MTOK, 768, 256, 256, 0);     // qkv fp16
        attn_mma_kernel<<<BATCH * 2, 256, ATTN_SMEM>>>(pqkv, po);
        sgemm(po, Wout, Bout, px, py, 0, MTOK, 256, 256, 256, 0);      // py = x + attn
        ln_kernel<<<MTOK / 8, 256>>>(px, py, ln1_g + l * DM, ln1_b + l * DM);
        sgemm(px, W1, B1, 0, pff, 0, MTOK, 1024, 256, 256, 1);
        sgemm(pff, W2, B2, px, py, 0, MTOK, 256, 1024, 1024, 0);       // py = x + ff
        ln_kernel<<<MTOK / 8, 256>>>(px, py, ln2_g + l * DM, ln2_b + l * DM);
    }

    // heads
    pool_kernel<<<BATCH, DM>>>(px, ppool);

    sgemm(ppool, vw1, vb1, 0, pvh, 0, BATCH, 256, 256, 256, 1);
    head_final_kernel<<<BATCH, 32>>>(pvh, vw2, vb2, out_value, 1, 1);

    // policy: split-K=2 over K=16384 (x viewed as [B, 64*256])
    sgemm(px,        pw1,        0, 0, ph1a, 0, BATCH, 1024, 8192, 16384, 0);
    sgemm(px + 8192, pw1 + 8192, 0, 0, ph1b, 0, BATCH, 1024, 8192, 16384, 0);
    combine_relu_kernel<<<BATCH * 1024 / 4 / 256, 256>>>(ph1a, ph1b, pb1, ph1);
    sgemm(ph1, pw2, pb2, 0, out_policy, 0, BATCH, 4096, 1024, 1024, 0);

    sgemm(ppool, cw1, cb1, 0, pch, 0, BATCH, 256, 256, 256, 1);
    head_final_kernel<<<BATCH, 32>>>(pch, cw2, cb2, out_class, 3, 0);
}